// round 4
// baseline (speedup 1.0000x reference)
#include <cuda_runtime.h>

#define BATCH   8
#define CH      512
#define SEQ     1024
#define NH      8
#define HD      64
#define QKV_DIM 1536

typedef unsigned long long ull;

// ---- f32x2 packed-math helpers (sm_100+; FFMA2 not emitted by ptxas from C++) ----
__device__ __forceinline__ ull fma2(ull a, ull b, ull c) {
    ull d;
    asm("fma.rn.f32x2 %0, %1, %2, %3;" : "=l"(d) : "l"(a), "l"(b), "l"(c));
    return d;
}
__device__ __forceinline__ ull mul2(ull a, ull b) {
    ull d;
    asm("mul.rn.f32x2 %0, %1, %2;" : "=l"(d) : "l"(a), "l"(b));
    return d;
}
__device__ __forceinline__ ull splat2(float v) {
    ull d;
    asm("mov.b64 %0, {%1, %1};" : "=l"(d) : "f"(v));
    return d;
}
__device__ __forceinline__ float2 unpack2(ull v) {
    float2 r;
    asm("mov.b64 {%0, %1}, %2;" : "=f"(r.x), "=f"(r.y) : "l"(v));
    return r;
}

// Scratch (allocation-free rule: __device__ globals)
__device__ float g_qkv[BATCH * SEQ * QKV_DIM];   // [b][n][3C]
__device__ float g_att[BATCH * SEQ * CH];        // [b][n][C]

// ---------------------------------------------------------------------------
// Kernel 1: QKV projection. qkv[b][n][j] = sum_c x[b][c][n]*Wqkv[j][c] + bqkv[j]
// M=8192 (b,n), N=1536 (j), K=512. Tile 128x128x8, 256 thr, 8x8 micro, dbl-buf.
// ---------------------------------------------------------------------------
__global__ void __launch_bounds__(256)
qkv_gemm(const float* __restrict__ x,
         const float* __restrict__ Wqkv,
         const float* __restrict__ bqkv)
{
    const int jt = blockIdx.x;            // 0..11
    const int mt = blockIdx.y;            // 0..63
    const int b  = mt >> 3;
    const int n0 = (mt & 7) * 128;
    const int j0 = jt * 128;
    const int t  = threadIdx.x;
    const int nx = t & 15;                // n-dim of microtile
    const int my = t >> 4;                // m-dim of microtile

    __shared__ float As[2][8][128];       // [k][m]
    __shared__ float Bs[2][8][128];       // [k][j]

    const float* xb = x + (size_t)b * CH * SEQ;

    // loader indices
    const int ak  = t >> 5;               // 0..7
    const int am  = (t & 31) * 4;
    const int bj  = t & 127;
    const int bk4 = (t >> 7) * 4;         // 0 or 4

    ull acc[4][8];
    #pragma unroll
    for (int p = 0; p < 4; p++)
        #pragma unroll
        for (int n = 0; n < 8; n++) acc[p][n] = 0ull;

    float4 av, bv;
    // prologue: chunk 0
    av = *(const float4*)&xb[(size_t)ak * SEQ + n0 + am];
    bv = *(const float4*)&Wqkv[(size_t)(j0 + bj) * CH + bk4];
    *(float4*)&As[0][ak][am] = av;
    Bs[0][bk4 + 0][bj] = bv.x;
    Bs[0][bk4 + 1][bj] = bv.y;
    Bs[0][bk4 + 2][bj] = bv.z;
    Bs[0][bk4 + 3][bj] = bv.w;
    __syncthreads();

    const int NK = CH / 8;                // 64
    for (int kc = 0; kc < NK; kc++) {
        const int buf = kc & 1;
        if (kc + 1 < NK) {
            const int k0 = (kc + 1) * 8;
            av = *(const float4*)&xb[(size_t)(k0 + ak) * SEQ + n0 + am];
            bv = *(const float4*)&Wqkv[(size_t)(j0 + bj) * CH + k0 + bk4];
        }
        #pragma unroll
        for (int k = 0; k < 8; k++) {
            ulonglong2 a01 = *(const ulonglong2*)&As[buf][k][my * 8];
            ulonglong2 a23 = *(const ulonglong2*)&As[buf][k][my * 8 + 4];
            ull ap[4] = {a01.x, a01.y, a23.x, a23.y};
            float4 b0 = *(const float4*)&Bs[buf][k][nx * 4];
            float4 b1 = *(const float4*)&Bs[buf][k][64 + nx * 4];
            ull sb[8] = {splat2(b0.x), splat2(b0.y), splat2(b0.z), splat2(b0.w),
                         splat2(b1.x), splat2(b1.y), splat2(b1.z), splat2(b1.w)};
            #pragma unroll
            for (int p = 0; p < 4; p++)
                #pragma unroll
                for (int n = 0; n < 8; n++)
                    acc[p][n] = fma2(ap[p], sb[n], acc[p][n]);
        }
        if (kc + 1 < NK) {
            const int nb = (kc + 1) & 1;
            *(float4*)&As[nb][ak][am] = av;
            Bs[nb][bk4 + 0][bj] = bv.x;
            Bs[nb][bk4 + 1][bj] = bv.y;
            Bs[nb][bk4 + 2][bj] = bv.z;
            Bs[nb][bk4 + 3][bj] = bv.w;
            __syncthreads();
        }
    }

    // epilogue
    float* outb = g_qkv + (size_t)b * SEQ * QKV_DIM;
    #pragma unroll
    for (int r = 0; r < 8; r++) {
        const int p   = r >> 1;
        const int sel = r & 1;
        const int nn  = n0 + my * 8 + r;
        #pragma unroll
        for (int hh = 0; hh < 2; hh++) {
            const int jj = j0 + hh * 64 + nx * 4;
            float4 bias = *(const float4*)&bqkv[jj];
            float2 e0 = unpack2(acc[p][hh * 4 + 0]);
            float2 e1 = unpack2(acc[p][hh * 4 + 1]);
            float2 e2 = unpack2(acc[p][hh * 4 + 2]);
            float2 e3 = unpack2(acc[p][hh * 4 + 3]);
            float4 rgt;
            rgt.x = (sel ? e0.y : e0.x) + bias.x;
            rgt.y = (sel ? e1.y : e1.x) + bias.y;
            rgt.z = (sel ? e2.y : e2.x) + bias.z;
            rgt.w = (sel ? e3.y : e3.x) + bias.w;
            *(float4*)&outb[(size_t)nn * QKV_DIM + jj] = rgt;
        }
    }
}

// ---------------------------------------------------------------------------
// Kernel 2: causal flash attention. 2 threads per query row (adjacent lanes,
// each owns 32 dims; shfl_xor(1) combines partial dots). 256 thr / 128 rows.
// K/V staged 32x64 in SMEM; 16-key subblocks keep s[] live range short.
// ---------------------------------------------------------------------------
__global__ void __launch_bounds__(256)
attn_kernel()
{
    const int qt   = blockIdx.x;           // 0..7
    const int bh   = blockIdx.y;           // 0..63
    const int b    = bh >> 3;
    const int h    = bh & 7;
    const int tid  = threadIdx.x;          // 0..255
    const int r    = tid >> 1;             // query row in tile
    const int half = tid & 1;
    const int i    = qt * 128 + r;
    const int d0   = half * 32;

    const float* qkvb = g_qkv + (size_t)b * SEQ * QKV_DIM;
    const float scale = 0.125f;

    __shared__ float Ks[32 * 64];
    __shared__ float Vs[32 * 64];

    ull q2[16], o2[16];
    {
        const ulonglong2* qrow =
            (const ulonglong2*)(qkvb + (size_t)i * QKV_DIM + h * HD + d0);
        #pragma unroll
        for (int d = 0; d < 8; d++) {
            ulonglong2 v = qrow[d];
            q2[2 * d] = v.x; q2[2 * d + 1] = v.y;
        }
        #pragma unroll
        for (int d = 0; d < 16; d++) o2[d] = 0ull;
    }

    float mrun = -1e30f, l = 0.f;

    const int nkb = (qt + 1) * 4;
    for (int kb = 0; kb < nkb; kb++) {
        const int k0 = kb * 32;
        #pragma unroll
        for (int u = 0; u < 2; u++) {      // cooperative K/V load
            int f   = u * 256 + tid;       // 0..511 float4 slots
            int row = f >> 4;
            int c4  = f & 15;
            const float* base = qkvb + (size_t)(k0 + row) * QKV_DIM + h * HD;
            ((float4*)Ks)[row * 16 + c4] = ((const float4*)(base + CH))[c4];
            ((float4*)Vs)[row * 16 + c4] = ((const float4*)(base + 2 * CH))[c4];
        }
        __syncthreads();

        #pragma unroll
        for (int sb = 0; sb < 2; sb++) {
            float s[16];
            #pragma unroll
            for (int jj = 0; jj < 16; jj++) {
                const int j = sb * 16 + jj;
                const ulonglong2* kr = (const ulonglong2*)(Ks + j * 64 + d0);
                ull a = 0ull;
                #pragma unroll
                for (int dd = 0; dd < 8; dd++) {
                    ulonglong2 kv = kr[dd];               // broadcast LDS
                    a = fma2(q2[2 * dd],     kv.x, a);
                    a = fma2(q2[2 * dd + 1], kv.y, a);
                }
                float2 ac = unpack2(a);
                float part = ac.x + ac.y;
                float full = part + __shfl_xor_sync(0xffffffff, part, 1);
                s[jj] = (k0 + j <= i) ? full * scale : -1e30f;
            }
            float mb = s[0];
            #pragma unroll
            for (int jj = 1; jj < 16; jj++) mb = fmaxf(mb, s[jj]);
            float mnew  = fmaxf(mrun, mb);
            float alpha = __expf(mrun - mnew);
            l *= alpha;
            ull a2 = splat2(alpha);
            #pragma unroll
            for (int d = 0; d < 16; d++) o2[d] = mul2(o2[d], a2);
            #pragma unroll
            for (int jj = 0; jj < 16; jj++) {
                const int j = sb * 16 + jj;
                float p = __expf(s[jj] - mnew);
                l += p;
                ull p2 = splat2(p);
                const ulonglong2* vr = (const ulonglong2*)(Vs + j * 64 + d0);
                #pragma unroll
                for (int dd = 0; dd < 8; dd++) {
                    ulonglong2 vv = vr[dd];               // broadcast LDS
                    o2[2 * dd]     = fma2(p2, vv.x, o2[2 * dd]);
                    o2[2 * dd + 1] = fma2(p2, vv.y, o2[2 * dd + 1]);
                }
            }
            mrun = mnew;
        }
        __syncthreads();
    }

    const float inv = 1.f / l;
    float* orow = g_att + ((size_t)b * SEQ + i) * CH + h * HD + d0;
    #pragma unroll
    for (int d = 0; d < 8; d++) {
        float2 a = unpack2(o2[2 * d]);
        float2 c = unpack2(o2[2 * d + 1]);
        float4 rr = make_float4(a.x * inv, a.y * inv, c.x * inv, c.y * inv);
        ((float4*)orow)[d] = rr;
    }
}

// ---------------------------------------------------------------------------
// Kernel 3: output projection + transpose to NCHW.
// out[b][j][n] = sum_c g_att[b][n][c]*Wp[j][c] + bp[j]
// Micro-tile: nx -> tokens (coalesced store), my -> out-channels.
// ---------------------------------------------------------------------------
__global__ void __launch_bounds__(256)
proj_gemm(const float* __restrict__ Wp,
          const float* __restrict__ bp,
          float* __restrict__ out)
{
    const int jt = blockIdx.x;            // 0..3
    const int mt = blockIdx.y;            // 0..63
    const int b  = mt >> 3;
    const int n0 = (mt & 7) * 128;
    const int j0 = jt * 128;
    const int t  = threadIdx.x;
    const int nx = t & 15;                // token dim
    const int my = t >> 4;                // channel dim

    __shared__ float As[2][8][128];       // [k][m] tokens
    __shared__ float Bs[2][8][128];       // [k][j] channels

    const float* A = g_att + (size_t)b * SEQ * CH;

    const int am  = t & 127;
    const int k4  = (t >> 7) * 4;         // 0 or 4

    ull acc[4][8];                        // [j-pair][token-col]
    #pragma unroll
    for (int p = 0; p < 4; p++)
        #pragma unroll
        for (int n = 0; n < 8; n++) acc[p][n] = 0ull;

    float4 av, bv;
    av = *(const float4*)&A[(size_t)(n0 + am) * CH + k4];
    bv = *(const float4*)&Wp[(size_t)(j0 + am) * CH + k4];
    #pragma unroll
    for (int u = 0; u < 4; u++) {
        As[0][k4 + u][am] = ((const float*)&av)[u];
        Bs[0][k4 + u][am] = ((const float*)&bv)[u];
    }
    __syncthreads();

    const int NK = CH / 8;
    for (int kc = 0; kc < NK; kc++) {
        const int buf = kc & 1;
        if (kc + 1 < NK) {
            const int k0 = (kc + 1) * 8;
            av = *(const float4*)&A[(size_t)(n0 + am) * CH + k0 + k4];
            bv = *(const float4*)&Wp[(size_t)(j0 + am) * CH + k0 + k4];
        }
        #pragma unroll
        for (int k = 0; k < 8; k++) {
            ulonglong2 b01 = *(const ulonglong2*)&Bs[buf][k][my * 8];
            ulonglong2 b23 = *(const ulonglong2*)&Bs[buf][k][my * 8 + 4];
            ull bpair[4] = {b01.x, b01.y, b23.x, b23.y};
            float4 a0 = *(const float4*)&As[buf][k][nx * 4];
            float4 a1 = *(const float4*)&As[buf][k][64 + nx * 4];
            ull sa[8] = {splat2(a0.x), splat2(a0.y), splat2(a0.z), splat2(a0.w),
                         splat2(a1.x), splat2(a1.y), splat2(a1.z), splat2(a1.w)};
            #pragma unroll
            for (int p = 0; p < 4; p++)
                #pragma unroll
                for (int n = 0; n < 8; n++)
                    acc[p][n] = fma2(bpair[p], sa[n], acc[p][n]);
        }
        if (kc + 1 < NK) {
            const int nb = (kc + 1) & 1;
            #pragma unroll
            for (int u = 0; u < 4; u++) {
                As[nb][k4 + u][am] = ((const float*)&av)[u];
                Bs[nb][k4 + u][am] = ((const float*)&bv)[u];
            }
            __syncthreads();
        }
    }

    float* outb = out + (size_t)b * CH * SEQ;
    #pragma unroll
    for (int rr = 0; rr < 8; rr++) {
        const int p   = rr >> 1;
        const int sel = rr & 1;
        const int jg  = j0 + my * 8 + rr;
        const float bias = bp[jg];
        #pragma unroll
        for (int mh = 0; mh < 2; mh++) {
            float2 e0 = unpack2(acc[p][mh * 4 + 0]);
            float2 e1 = unpack2(acc[p][mh * 4 + 1]);
            float2 e2 = unpack2(acc[p][mh * 4 + 2]);
            float2 e3 = unpack2(acc[p][mh * 4 + 3]);
            float4 v;
            v.x = (sel ? e0.y : e0.x) + bias;
            v.y = (sel ? e1.y : e1.x) + bias;
            v.z = (sel ? e2.y : e2.x) + bias;
            v.w = (sel ? e3.y : e3.x) + bias;
            *(float4*)&outb[(size_t)jg * SEQ + n0 + mh * 64 + nx * 4] = v;
        }
    }
}

// ---------------------------------------------------------------------------
extern "C" void kernel_launch(void* const* d_in, const int* in_sizes, int n_in,
                              void* d_out, int out_size)
{
    const float* x    = (const float*)d_in[0];
    const float* Wqkv = (const float*)d_in[1];
    const float* bqkv = (const float*)d_in[2];
    const float* Wp   = (const float*)d_in[3];
    const float* bp   = (const float*)d_in[4];
    float* out = (float*)d_out;
    (void)in_sizes; (void)n_in; (void)out_size;

    qkv_gemm<<<dim3(QKV_DIM / 128, (BATCH * SEQ) / 128), 256>>>(x, Wqkv, bqkv);
    attn_kernel<<<dim3(SEQ / 128, BATCH * NH), 256>>>();
    proj_gemm<<<dim3(CH / 128, (BATCH * SEQ) / 128), 256>>>(Wp, bp, out);
}

// round 9
// speedup vs baseline: 1.2432x; 1.2432x over previous
#include <cuda_runtime.h>
#include <cuda_bf16.h>

#define BATCH   8
#define CH      512
#define SEQ     1024
#define NH      8
#define HD      64
#define QKV_DIM 1536
#define NTOK    (BATCH * SEQ)     // 8192

typedef unsigned long long ull;
typedef unsigned int u32;

// ---------------- f32x2 packed helpers ----------------
__device__ __forceinline__ ull fma2(ull a, ull b, ull c) {
    ull d; asm("fma.rn.f32x2 %0, %1, %2, %3;" : "=l"(d) : "l"(a), "l"(b), "l"(c)); return d;
}
__device__ __forceinline__ ull mul2(ull a, ull b) {
    ull d; asm("mul.rn.f32x2 %0, %1, %2;" : "=l"(d) : "l"(a), "l"(b)); return d;
}
__device__ __forceinline__ ull splat2(float v) {
    ull d; asm("mov.b64 %0, {%1, %1};" : "=l"(d) : "f"(v)); return d;
}
__device__ __forceinline__ float2 unpack2(ull v) {
    float2 r; asm("mov.b64 {%0, %1}, %2;" : "=f"(r.x), "=f"(r.y) : "l"(v)); return r;
}

__device__ __forceinline__ u32 smem_u32(const void* p) {
    u32 a;
    asm("{ .reg .u64 t; cvta.to.shared.u64 t, %1; cvt.u32.u64 %0, t; }" : "=r"(a) : "l"(p));
    return a;
}

// ---------------- warp MMA helpers (baseline PTX, sm_80+) ----------------
__device__ __forceinline__ void ldmx4(u32 addr, u32* r) {
    asm volatile("ldmatrix.sync.aligned.m8n8.x4.shared.b16 {%0,%1,%2,%3}, [%4];"
                 : "=r"(r[0]), "=r"(r[1]), "=r"(r[2]), "=r"(r[3]) : "r"(addr));
}
__device__ __forceinline__ void ldmx2(u32 addr, u32* r) {
    asm volatile("ldmatrix.sync.aligned.m8n8.x2.shared.b16 {%0,%1}, [%2];"
                 : "=r"(r[0]), "=r"(r[1]) : "r"(addr));
}
__device__ __forceinline__ void mma_bf16(float* d, const u32* a, const u32* b) {
    asm volatile("mma.sync.aligned.m16n8k16.row.col.f32.bf16.bf16.f32 "
                 "{%0,%1,%2,%3}, {%4,%5,%6,%7}, {%8,%9}, {%0,%1,%2,%3};"
                 : "+f"(d[0]), "+f"(d[1]), "+f"(d[2]), "+f"(d[3])
                 : "r"(a[0]), "r"(a[1]), "r"(a[2]), "r"(a[3]), "r"(b[0]), "r"(b[1]));
}

// ---------------- global scratch ----------------
__device__ float g_qkv[NTOK * QKV_DIM];          // [token][3C]
__device__ float g_att[NTOK * CH];               // [token][C]
__device__ __nv_bfloat16 g_xT_hi[NTOK * CH], g_xT_lo[NTOK * CH];       // x^T [token][c]
__device__ __nv_bfloat16 g_wq_hi[QKV_DIM * CH], g_wq_lo[QKV_DIM * CH];
__device__ __nv_bfloat16 g_wp_hi[CH * CH],      g_wp_lo[CH * CH];
__device__ __nv_bfloat16 g_at_hi[NTOK * CH],    g_at_lo[NTOK * CH];

// ---------------- split-convert: fp32 -> bf16 hi + residual lo ----------------
__global__ void conv_split(int which, const float* __restrict__ src, int n)
{
    int i = blockIdx.x * 256 + threadIdx.x;
    if (i >= n) return;
    __nv_bfloat16 *hi, *lo;
    const float* s = src;
    if (which == 0)      { hi = g_wq_hi; lo = g_wq_lo; }
    else if (which == 1) { hi = g_wp_hi; lo = g_wp_lo; }
    else                 { hi = g_at_hi; lo = g_at_lo; s = g_att; }
    float v = s[i];
    __nv_bfloat16 h = __float2bfloat16(v);
    float r = v - __bfloat162float(h);
    hi[i] = h;
    lo[i] = __float2bfloat16(r);
}

// ---------------- transpose-convert x[b][c][n] -> xT[(b,n)][c] hi/lo ----------------
__global__ void convT_x(const float* __restrict__ x)
{
    __shared__ float t[32][33];
    const int b  = blockIdx.z;
    const int n0 = blockIdx.x * 32;
    const int c0 = blockIdx.y * 32;
    const int tx = threadIdx.x, ty = threadIdx.y;
    #pragma unroll
    for (int i = 0; i < 4; i++)
        t[ty + i * 8][tx] = x[((size_t)b * CH + c0 + ty + i * 8) * SEQ + n0 + tx];
    __syncthreads();
    #pragma unroll
    for (int i = 0; i < 4; i++) {
        float v = t[tx][ty + i * 8];
        size_t idx = ((size_t)b * SEQ + n0 + ty + i * 8) * CH + c0 + tx;
        __nv_bfloat16 h = __float2bfloat16(v);
        g_xT_hi[idx] = h;
        g_xT_lo[idx] = __float2bfloat16(v - __bfloat162float(h));
    }
}

// ---------------------------------------------------------------------------
// mma.sync GEMM, bf16x3 split (hi*hi + hi*lo + lo*hi), fp32 accumulate.
// D[m][n] = sum_k A[m][k] * B[n][k]   (both K-major)
// MODE 0 (qkv):  A = xT[8192][512] (m=tok), B = Wqkv[1536][512] (n=j)
//                -> g_qkv[tok][j] = D + bqkv[j]
// MODE 1 (proj): A = att_split[8192->? no: A = Wp? see below]
//                A = Wp[512][512] (m=ch), B = att[8192][512] (n=tok)
//                -> out[b][ch][n'] = D + bp[ch]
// CTA tile 128x128, 8 warps of 64(m)x32(n). K-chunk 32 in SMEM, stride 40 bf16.
// ---------------------------------------------------------------------------
#define KST 40    // smem row stride in bf16 (80 bytes)

template <int MODE>
__global__ void __launch_bounds__(256) gemm_mma(const float* __restrict__ bias,
                                                float* __restrict__ outp)
{
    constexpr int KDIM = 512;
    constexpr int NCHK = KDIM / 32;       // 16
    const int n0  = blockIdx.x * 128;
    const int m0  = blockIdx.y * 128;
    const int tid = threadIdx.x;
    const int w   = tid >> 5;
    const int lane = tid & 31;
    const int mw = (w & 1) * 64;          // warp m-offset in tile
    const int nw = (w >> 1) * 32;         // warp n-offset in tile

    __shared__ __align__(16) __nv_bfloat16 sAhi[128 * KST];
    __shared__ __align__(16) __nv_bfloat16 sAlo[128 * KST];
    __shared__ __align__(16) __nv_bfloat16 sBhi[128 * KST];
    __shared__ __align__(16) __nv_bfloat16 sBlo[128 * KST];

    const __nv_bfloat16 *Ahi, *Alo, *Bhi, *Blo;
    if (MODE == 0) { Ahi = g_xT_hi; Alo = g_xT_lo; Bhi = g_wq_hi; Blo = g_wq_lo; }
    else           { Ahi = g_wp_hi; Alo = g_wp_lo; Bhi = g_at_hi; Blo = g_at_lo; }

    float acc[4][4][4];
    #pragma unroll
    for (int mf = 0; mf < 4; mf++)
        #pragma unroll
        for (int nf = 0; nf < 4; nf++)
            #pragma unroll
            for (int e = 0; e < 4; e++) acc[mf][nf][e] = 0.f;

    // ldmatrix per-lane address bases (byte offsets within a chunk image)
    const u32 aBaseHi = smem_u32(sAhi) + (u32)((mw + (lane & 15)) * (KST * 2) + (lane >> 4) * 16);
    const u32 aBaseLo = smem_u32(sAlo) + (u32)((mw + (lane & 15)) * (KST * 2) + (lane >> 4) * 16);
    const u32 bRow    = (u32)((nw + (lane & 7)) * (KST * 2) + ((lane >> 3) & 1) * 16);
    const u32 bBaseHi = smem_u32(sBhi) + bRow;
    const u32 bBaseLo = smem_u32(sBlo) + bRow;

    // loader indices: per array, 2 uint4 per thread per chunk
    // idx = u*256+tid; row = idx>>2; c = idx&3 (uint4 col = 8 bf16)
    for (int kc = 0; kc < NCHK; kc++) {
        const int k0 = kc * 32;
        __syncthreads();
        #pragma unroll
        for (int u = 0; u < 2; u++) {
            int idx = u * 256 + tid;
            int row = idx >> 2, c = idx & 3;
            size_t srcA = (size_t)(m0 + row) * KDIM + k0 + c * 8;
            size_t srcB = (size_t)(n0 + row) * KDIM + k0 + c * 8;
            u32 dst = row * KST + c * 8;
            *(uint4*)&sAhi[dst] = *(const uint4*)&Ahi[srcA];
            *(uint4*)&sAlo[dst] = *(const uint4*)&Alo[srcA];
            *(uint4*)&sBhi[dst] = *(const uint4*)&Bhi[srcB];
            *(uint4*)&sBlo[dst] = *(const uint4*)&Blo[srcB];
        }
        __syncthreads();

        #pragma unroll
        for (int ks = 0; ks < 2; ks++) {
            u32 ahi[4][4], alo[4][4];
            #pragma unroll
            for (int mf = 0; mf < 4; mf++) {
                ldmx4(aBaseHi + mf * (16 * KST * 2) + ks * 32, ahi[mf]);
                ldmx4(aBaseLo + mf * (16 * KST * 2) + ks * 32, alo[mf]);
            }
            #pragma unroll
            for (int nf = 0; nf < 4; nf++) {
                u32 bh[2], bl[2];
                ldmx2(bBaseHi + nf * (8 * KST * 2) + ks * 32, bh);
                ldmx2(bBaseLo + nf * (8 * KST * 2) + ks * 32, bl);
                #pragma unroll
                for (int mf = 0; mf < 4; mf++) {
                    mma_bf16(acc[mf][nf], ahi[mf], bh);
                    mma_bf16(acc[mf][nf], ahi[mf], bl);
                    mma_bf16(acc[mf][nf], alo[mf], bh);
                }
            }
        }
    }

    // ---- epilogue: d0,d1 -> (m=g, n=tg*2,+1); d2,d3 -> (m=g+8, same n)
    const int g  = lane >> 2;
    const int tg = lane & 3;
    #pragma unroll
    for (int mf = 0; mf < 4; mf++) {
        const int mA = m0 + mw + mf * 16 + g;
        const int mB = mA + 8;
        #pragma unroll
        for (int nf = 0; nf < 4; nf++) {
            const int nn = n0 + nw + nf * 8 + tg * 2;
            if (MODE == 0) {
                float2 bb = *(const float2*)&bias[nn];
                float2 v0 = make_float2(acc[mf][nf][0] + bb.x, acc[mf][nf][1] + bb.y);
                float2 v1 = make_float2(acc[mf][nf][2] + bb.x, acc[mf][nf][3] + bb.y);
                *(float2*)&g_qkv[(size_t)mA * QKV_DIM + nn] = v0;
                *(float2*)&g_qkv[(size_t)mB * QKV_DIM + nn] = v1;
            } else {
                const int bb_ = nn >> 10, np = nn & 1023;
                float biasA = bias[mA], biasB = bias[mB];
                float* ob = outp + (size_t)bb_ * CH * SEQ + np;
                *(float2*)&ob[(size_t)mA * SEQ] =
                    make_float2(acc[mf][nf][0] + biasA, acc[mf][nf][1] + biasA);
                *(float2*)&ob[(size_t)mB * SEQ] =
                    make_float2(acc[mf][nf][2] + biasB, acc[mf][nf][3] + biasB);
            }
        }
    }
}

// ---------------------------------------------------------------------------
// Causal flash attention: 1 thread per query row, fma2 arithmetic.
// grid (8 q-tiles, 64 b*h), block 128. K/V staged 32x64 in SMEM (broadcast LDS).
// ---------------------------------------------------------------------------
__global__ void __launch_bounds__(128) attn_kernel()
{
    const int qt  = blockIdx.x;
    const int bh  = blockIdx.y;
    const int b   = bh >> 3;
    const int h   = bh & 7;
    const int tid = threadIdx.x;
    const int i   = qt * 128 + tid;

    const float* qkvb = g_qkv + (size_t)b * SEQ * QKV_DIM;
    const float scale = 0.125f;

    __shared__ float Ks[32 * 64];
    __shared__ float Vs[32 * 64];

    ull q2[32], o2[32];
    {
        const ulonglong2* qr = (const ulonglong2*)(qkvb + (size_t)i * QKV_DIM + h * HD);
        #pragma unroll
        for (int d = 0; d < 16; d++) {
            ulonglong2 v = qr[d];
            q2[2 * d] = v.x; q2[2 * d + 1] = v.y;
        }
        #pragma unroll
        for (int d = 0; d < 32; d++) o2[d] = 0ull;
    }

    float mrun = -1e30f, l = 0.f;
    const int nkb = (qt + 1) * 4;

    for (int kb = 0; kb < nkb; kb++) {
        const int k0 = kb * 32;
        #pragma unroll
        for (int u = 0; u < 4; u++) {
            int f   = u * 128 + tid;
            int row = f >> 4;
            int c4  = f & 15;
            const float* base = qkvb + (size_t)(k0 + row) * QKV_DIM + h * HD;
            ((float4*)Ks)[f] = ((const float4*)(base + CH))[c4];
            ((float4*)Vs)[f] = ((const float4*)(base + 2 * CH))[c4];
        }
        __syncthreads();

        #pragma unroll
        for (int sb = 0; sb < 2; sb++) {
            float s[16];
            #pragma unroll
            for (int jj = 0; jj < 16; jj++) {
                const int j = sb * 16 + jj;
                const ulonglong2* kr = (const ulonglong2*)(Ks + j * 64);
                ull a0 = 0ull, a1 = 0ull;
                #pragma unroll
                for (int dd = 0; dd < 16; dd++) {
                    ulonglong2 kv = kr[dd];                 // broadcast LDS.128
                    a0 = fma2(q2[2 * dd],     kv.x, a0);
                    a1 = fma2(q2[2 * dd + 1], kv.y, a1);
                }
                float2 x0 = unpack2(a0), x1 = unpack2(a1);
                float sv = (x0.x + x0.y) + (x1.x + x1.y);
                s[jj] = (k0 + j <= i) ? sv * scale : -1e30f;
            }
            float mb = s[0];
            #pragma unroll
            for (int jj = 1; jj < 16; jj++) mb = fmaxf(mb, s[jj]);
            float mnew  = fmaxf(mrun, mb);
            float alpha = __expf(mrun - mnew);
            l *= alpha;
            ull a2 = splat2(alpha);
            #pragma unroll
            for (int d = 0; d < 32; d++) o2[d] = mul2(o2[d], a2);
            #pragma unroll
            for (int jj = 0; jj < 16; jj++) {
                const int j = sb * 16 + jj;
                float p = __expf(s[jj] - mnew);
                l += p;
                ull p2 = splat2(p);
                const ulonglong2* vr = (const ulonglong2*)(Vs + j * 64);
                #pragma unroll
                for (int dd = 0; dd < 16; dd++) {
                    ulonglong2 vv = vr[dd];                 // broadcast LDS.128
                    o2[2 * dd]     = fma2(p2, vv.x, o2[2 * dd]);
                    o2[2 * dd + 1] = fma2(p2, vv.y, o2[2 * dd + 1]);
                }
            }
            mrun = mnew;
        }
        __syncthreads();
    }

    const float inv = 1.f / l;
    float* orow = g_att + ((size_t)b * SEQ + i) * CH + h * HD;
    #pragma unroll
    for (int d = 0; d < 16; d++) {
        float2 a = unpack2(o2[2 * d]);
        float2 c = unpack2(o2[2 * d + 1]);
        ((float4*)orow)[d] = make_float4(a.x * inv, a.y * inv, c.x * inv, c.y * inv);
    }
}

// ---------------------------------------------------------------------------
extern "C" void kernel_launch(void* const* d_in, const int* in_sizes, int n_in,
                              void* d_out, int out_size)
{
    const float* x    = (const float*)d_in[0];
    const float* Wqkv = (const float*)d_in[1];
    const float* bqkv = (const float*)d_in[2];
    const float* Wp   = (const float*)d_in[3];
    const float* bp   = (const float*)d_in[4];
    float* out = (float*)d_out;
    (void)in_sizes; (void)n_in; (void)out_size;

    conv_split<<<(QKV_DIM * CH + 255) / 256, 256>>>(0, Wqkv, QKV_DIM * CH);
    conv_split<<<(CH * CH + 255) / 256, 256>>>(1, Wp, CH * CH);
    convT_x<<<dim3(SEQ / 32, CH / 32, BATCH), dim3(32, 8)>>>(x);

    // qkv: m = tokens (8192), n = qkv features (1536)
    gemm_mma<0><<<dim3(QKV_DIM / 128, NTOK / 128), 256>>>(bqkv, out);  // -> g_qkv
    attn_kernel<<<dim3(SEQ / 128, BATCH * NH), 128>>>();               // -> g_att
    conv_split<<<(NTOK * CH + 255) / 256, 256>>>(2, nullptr, NTOK * CH);
    // proj: m = channels (512), n = tokens (8192)
    gemm_mma<1><<<dim3(NTOK / 128, CH / 128), 256>>>(bp, out);         // -> out
}

// round 10
// speedup vs baseline: 1.4734x; 1.1852x over previous
#include <cuda_runtime.h>
#include <cuda_bf16.h>

#define BATCH   8
#define CH      512
#define SEQ     1024
#define NH      8
#define HD      64
#define QKV_DIM 1536
#define NTOK    (BATCH * SEQ)     // 8192
#define NBH     (BATCH * NH)      // 64

typedef unsigned long long ull;
typedef unsigned int u32;

__device__ __forceinline__ u32 smem_u32(const void* p) {
    u32 a;
    asm("{ .reg .u64 t; cvta.to.shared.u64 t, %1; cvt.u32.u64 %0, t; }" : "=r"(a) : "l"(p));
    return a;
}

// ---------------- warp MMA helpers (baseline PTX, sm_80+) ----------------
__device__ __forceinline__ void ldmx4(u32 addr, u32* r) {
    asm volatile("ldmatrix.sync.aligned.m8n8.x4.shared.b16 {%0,%1,%2,%3}, [%4];"
                 : "=r"(r[0]), "=r"(r[1]), "=r"(r[2]), "=r"(r[3]) : "r"(addr));
}
__device__ __forceinline__ void ldmx2(u32 addr, u32* r) {
    asm volatile("ldmatrix.sync.aligned.m8n8.x2.shared.b16 {%0,%1}, [%2];"
                 : "=r"(r[0]), "=r"(r[1]) : "r"(addr));
}
__device__ __forceinline__ void mma_bf16(float* d, const u32* a, const u32* b) {
    asm volatile("mma.sync.aligned.m16n8k16.row.col.f32.bf16.bf16.f32 "
                 "{%0,%1,%2,%3}, {%4,%5,%6,%7}, {%8,%9}, {%0,%1,%2,%3};"
                 : "+f"(d[0]), "+f"(d[1]), "+f"(d[2]), "+f"(d[3])
                 : "r"(a[0]), "r"(a[1]), "r"(a[2]), "r"(a[3]), "r"(b[0]), "r"(b[1]));
}

// ---------------- global scratch ----------------
__device__ float g_qkv[NTOK * QKV_DIM];          // [token][3C]
__device__ float g_att[NTOK * CH];               // [token][C]
__device__ __nv_bfloat16 g_xT_hi[NTOK * CH], g_xT_lo[NTOK * CH];
__device__ __nv_bfloat16 g_wq_hi[QKV_DIM * CH], g_wq_lo[QKV_DIM * CH];
__device__ __nv_bfloat16 g_wp_hi[CH * CH],      g_wp_lo[CH * CH];
__device__ __nv_bfloat16 g_at_hi[NTOK * CH],    g_at_lo[NTOK * CH];
// attention scratch
__device__ __nv_bfloat16 g_q_hi[NBH * SEQ * HD], g_q_lo[NBH * SEQ * HD];   // [bh][n][d]
__device__ __nv_bfloat16 g_k_hi[NBH * SEQ * HD], g_k_lo[NBH * SEQ * HD];   // [bh][n][d]
__device__ __nv_bfloat16 g_vt_hi[NBH * HD * SEQ], g_vt_lo[NBH * HD * SEQ]; // [bh][d][n]
__device__ float g_S[(size_t)NBH * SEQ * SEQ];                              // 256 MB
__device__ __nv_bfloat16 g_p_hi[(size_t)NBH * SEQ * SEQ];                   // 128 MB
__device__ __nv_bfloat16 g_p_lo[(size_t)NBH * SEQ * SEQ];                   // 128 MB

// ---------------- split-convert: fp32 -> bf16 hi + residual lo ----------------
__global__ void conv_split(int which, const float* __restrict__ src, int n)
{
    int i = blockIdx.x * 256 + threadIdx.x;
    if (i >= n) return;
    __nv_bfloat16 *hi, *lo;
    const float* s = src;
    if (which == 0)      { hi = g_wq_hi; lo = g_wq_lo; }
    else if (which == 1) { hi = g_wp_hi; lo = g_wp_lo; }
    else                 { hi = g_at_hi; lo = g_at_lo; s = g_att; }
    float v = s[i];
    __nv_bfloat16 h = __float2bfloat16(v);
    hi[i] = h;
    lo[i] = __float2bfloat16(v - __bfloat162float(h));
}

// ---------------- transpose-convert x[b][c][n] -> xT[(b,n)][c] hi/lo ----------------
__global__ void convT_x(const float* __restrict__ x)
{
    __shared__ float t[32][33];
    const int b  = blockIdx.z;
    const int n0 = blockIdx.x * 32;
    const int c0 = blockIdx.y * 32;
    const int tx = threadIdx.x, ty = threadIdx.y;
    #pragma unroll
    for (int i = 0; i < 4; i++)
        t[ty + i * 8][tx] = x[((size_t)b * CH + c0 + ty + i * 8) * SEQ + n0 + tx];
    __syncthreads();
    #pragma unroll
    for (int i = 0; i < 4; i++) {
        float v = t[tx][ty + i * 8];
        size_t idx = ((size_t)b * SEQ + n0 + ty + i * 8) * CH + c0 + tx;
        __nv_bfloat16 h = __float2bfloat16(v);
        g_xT_hi[idx] = h;
        g_xT_lo[idx] = __float2bfloat16(v - __bfloat162float(h));
    }
}

// ---------------- relayout q,k: g_qkv -> [bh][n][64] bf16 hi/lo ----------------
__global__ void relayout_qk()
{
    int idx = blockIdx.x * 256 + threadIdx.x;   // < NBH*SEQ*HD
    int d  = idx & 63;
    int n  = (idx >> 6) & 1023;
    int bh = idx >> 16;
    int b = bh >> 3, h = bh & 7;
    size_t src = ((size_t)(b * SEQ + n)) * QKV_DIM + h * HD + d;
    float q = g_qkv[src];
    float k = g_qkv[src + CH];
    __nv_bfloat16 qh = __float2bfloat16(q);
    __nv_bfloat16 kh = __float2bfloat16(k);
    g_q_hi[idx] = qh; g_q_lo[idx] = __float2bfloat16(q - __bfloat162float(qh));
    g_k_hi[idx] = kh; g_k_lo[idx] = __float2bfloat16(k - __bfloat162float(kh));
}

// ---------------- relayout v: g_qkv -> transposed [bh][d][n] bf16 hi/lo ----------------
__global__ void relayout_v()
{
    __shared__ float t[32][33];
    const int n0 = blockIdx.x * 32;
    const int d0 = blockIdx.y * 32;
    const int bh = blockIdx.z;
    const int b = bh >> 3, h = bh & 7;
    const int tx = threadIdx.x, ty = threadIdx.y;
    #pragma unroll
    for (int i = 0; i < 4; i++) {
        int n = n0 + ty + i * 8;
        t[ty + i * 8][tx] = g_qkv[((size_t)(b * SEQ + n)) * QKV_DIM + 2 * CH + h * HD + d0 + tx];
    }
    __syncthreads();
    #pragma unroll
    for (int i = 0; i < 4; i++) {
        float v = t[tx][ty + i * 8];
        size_t idx = (size_t)bh * HD * SEQ + (size_t)(d0 + ty + i * 8) * SEQ + n0 + tx;
        __nv_bfloat16 h2 = __float2bfloat16(v);
        g_vt_hi[idx] = h2;
        g_vt_lo[idx] = __float2bfloat16(v - __bfloat162float(h2));
    }
}

#define KST 40    // smem row stride in bf16 (80 bytes)

// ---------------------------------------------------------------------------
// Main GEMMs (unchanged from R9): bf16x3 split mma.sync.
// ---------------------------------------------------------------------------
template <int MODE>
__global__ void __launch_bounds__(256) gemm_mma(const float* __restrict__ bias,
                                                float* __restrict__ outp)
{
    constexpr int KDIM = 512;
    constexpr int NCHK = KDIM / 32;
    const int n0  = blockIdx.x * 128;
    const int m0  = blockIdx.y * 128;
    const int tid = threadIdx.x;
    const int w   = tid >> 5;
    const int lane = tid & 31;
    const int mw = (w & 1) * 64;
    const int nw = (w >> 1) * 32;

    __shared__ __align__(16) __nv_bfloat16 sAhi[128 * KST];
    __shared__ __align__(16) __nv_bfloat16 sAlo[128 * KST];
    __shared__ __align__(16) __nv_bfloat16 sBhi[128 * KST];
    __shared__ __align__(16) __nv_bfloat16 sBlo[128 * KST];

    const __nv_bfloat16 *Ahi, *Alo, *Bhi, *Blo;
    if (MODE == 0) { Ahi = g_xT_hi; Alo = g_xT_lo; Bhi = g_wq_hi; Blo = g_wq_lo; }
    else           { Ahi = g_wp_hi; Alo = g_wp_lo; Bhi = g_at_hi; Blo = g_at_lo; }

    float acc[4][4][4];
    #pragma unroll
    for (int mf = 0; mf < 4; mf++)
        #pragma unroll
        for (int nf = 0; nf < 4; nf++)
            #pragma unroll
            for (int e = 0; e < 4; e++) acc[mf][nf][e] = 0.f;

    const u32 aBaseHi = smem_u32(sAhi) + (u32)((mw + (lane & 15)) * (KST * 2) + (lane >> 4) * 16);
    const u32 aBaseLo = smem_u32(sAlo) + (u32)((mw + (lane & 15)) * (KST * 2) + (lane >> 4) * 16);
    const u32 bRow    = (u32)((nw + (lane & 7)) * (KST * 2) + ((lane >> 3) & 1) * 16);
    const u32 bBaseHi = smem_u32(sBhi) + bRow;
    const u32 bBaseLo = smem_u32(sBlo) + bRow;

    for (int kc = 0; kc < NCHK; kc++) {
        const int k0 = kc * 32;
        __syncthreads();
        #pragma unroll
        for (int u = 0; u < 2; u++) {
            int idx = u * 256 + tid;
            int row = idx >> 2, c = idx & 3;
            size_t srcA = (size_t)(m0 + row) * KDIM + k0 + c * 8;
            size_t srcB = (size_t)(n0 + row) * KDIM + k0 + c * 8;
            u32 dst = row * KST + c * 8;
            *(uint4*)&sAhi[dst] = *(const uint4*)&Ahi[srcA];
            *(uint4*)&sAlo[dst] = *(const uint4*)&Alo[srcA];
            *(uint4*)&sBhi[dst] = *(const uint4*)&Bhi[srcB];
            *(uint4*)&sBlo[dst] = *(const uint4*)&Blo[srcB];
        }
        __syncthreads();

        #pragma unroll
        for (int ks = 0; ks < 2; ks++) {
            u32 ahi[4][4], alo[4][4];
            #pragma unroll
            for (int mf = 0; mf < 4; mf++) {
                ldmx4(aBaseHi + mf * (16 * KST * 2) + ks * 32, ahi[mf]);
                ldmx4(aBaseLo + mf * (16 * KST * 2) + ks * 32, alo[mf]);
            }
            #pragma unroll
            for (int nf = 0; nf < 4; nf++) {
                u32 bh2[2], bl2[2];
                ldmx2(bBaseHi + nf * (8 * KST * 2) + ks * 32, bh2);
                ldmx2(bBaseLo + nf * (8 * KST * 2) + ks * 32, bl2);
                #pragma unroll
                for (int mf = 0; mf < 4; mf++) {
                    mma_bf16(acc[mf][nf], ahi[mf], bh2);
                    mma_bf16(acc[mf][nf], ahi[mf], bl2);
                    mma_bf16(acc[mf][nf], alo[mf], bh2);
                }
            }
        }
    }

    const int g  = lane >> 2;
    const int tg = lane & 3;
    #pragma unroll
    for (int mf = 0; mf < 4; mf++) {
        const int mA = m0 + mw + mf * 16 + g;
        const int mB = mA + 8;
        #pragma unroll
        for (int nf = 0; nf < 4; nf++) {
            const int nn = n0 + nw + nf * 8 + tg * 2;
            if (MODE == 0) {
                float2 bb = *(const float2*)&bias[nn];
                *(float2*)&g_qkv[(size_t)mA * QKV_DIM + nn] =
                    make_float2(acc[mf][nf][0] + bb.x, acc[mf][nf][1] + bb.y);
                *(float2*)&g_qkv[(size_t)mB * QKV_DIM + nn] =
                    make_float2(acc[mf][nf][2] + bb.x, acc[mf][nf][3] + bb.y);
            } else {
                const int bb_ = nn >> 10, np = nn & 1023;
                float biasA = bias[mA], biasB = bias[mB];
                float* ob = outp + (size_t)bb_ * CH * SEQ + np;
                *(float2*)&ob[(size_t)mA * SEQ] =
                    make_float2(acc[mf][nf][0] + biasA, acc[mf][nf][1] + biasA);
                *(float2*)&ob[(size_t)mB * SEQ] =
                    make_float2(acc[mf][nf][2] + biasB, acc[mf][nf][3] + biasB);
            }
        }
    }
}

// ---------------------------------------------------------------------------
// QK^T GEMM: S[bh][i][j] = scale * sum_d Q[i][d] K[j][d]  (causal tile-skip)
// grid (36 lower tiles, 64 bh), block 256; warp tile 64x32; K=64 (2 chunks).
// ---------------------------------------------------------------------------
__global__ void __launch_bounds__(256) gemm_qk()
{
    const int tId = blockIdx.x;
    const int bh  = blockIdx.y;
    int r = 0, accT = 0;
    while (accT + r + 1 <= tId) { accT += r + 1; r++; }
    const int c = tId - accT;

    const int tid = threadIdx.x;
    const int w   = tid >> 5;
    const int lane = tid & 31;
    const int mw = (w & 1) * 64;
    const int nw = (w >> 1) * 32;

    __shared__ __align__(16) __nv_bfloat16 sAhi[128 * KST];
    __shared__ __align__(16) __nv_bfloat16 sAlo[128 * KST];
    __shared__ __align__(16) __nv_bfloat16 sBhi[128 * KST];
    __shared__ __align__(16) __nv_bfloat16 sBlo[128 * KST];

    const __nv_bfloat16* Ahi = g_q_hi + (size_t)bh * SEQ * HD + (size_t)r * 128 * HD;
    const __nv_bfloat16* Alo = g_q_lo + (size_t)bh * SEQ * HD + (size_t)r * 128 * HD;
    const __nv_bfloat16* Bhi = g_k_hi + (size_t)bh * SEQ * HD + (size_t)c * 128 * HD;
    const __nv_bfloat16* Blo = g_k_lo + (size_t)bh * SEQ * HD + (size_t)c * 128 * HD;

    float acc[4][4][4];
    #pragma unroll
    for (int mf = 0; mf < 4; mf++)
        #pragma unroll
        for (int nf = 0; nf < 4; nf++)
            #pragma unroll
            for (int e = 0; e < 4; e++) acc[mf][nf][e] = 0.f;

    const u32 aBaseHi = smem_u32(sAhi) + (u32)((mw + (lane & 15)) * (KST * 2) + (lane >> 4) * 16);
    const u32 aBaseLo = smem_u32(sAlo) + (u32)((mw + (lane & 15)) * (KST * 2) + (lane >> 4) * 16);
    const u32 bRow    = (u32)((nw + (lane & 7)) * (KST * 2) + ((lane >> 3) & 1) * 16);
    const u32 bBaseHi = smem_u32(sBhi) + bRow;
    const u32 bBaseLo = smem_u32(sBlo) + bRow;

    #pragma unroll
    for (int kc = 0; kc < 2; kc++) {
        const int k0 = kc * 32;
        __syncthreads();
        #pragma unroll
        for (int u = 0; u < 2; u++) {
            int idx = u * 256 + tid;
            int row = idx >> 2, cc = idx & 3;
            size_t src = (size_t)row * HD + k0 + cc * 8;
            u32 dst = row * KST + cc * 8;
            *(uint4*)&sAhi[dst] = *(const uint4*)&Ahi[src];
            *(uint4*)&sAlo[dst] = *(const uint4*)&Alo[src];
            *(uint4*)&sBhi[dst] = *(const uint4*)&Bhi[src];
            *(uint4*)&sBlo[dst] = *(const uint4*)&Blo[src];
        }
        __syncthreads();

        #pragma unroll
        for (int ks = 0; ks < 2; ks++) {
            u32 ahi[4][4], alo[4][4];
            #pragma unroll
            for (int mf = 0; mf < 4; mf++) {
                ldmx4(aBaseHi + mf * (16 * KST * 2) + ks * 32, ahi[mf]);
                ldmx4(aBaseLo + mf * (16 * KST * 2) + ks * 32, alo[mf]);
            }
            #pragma unroll
            for (int nf = 0; nf < 4; nf++) {
                u32 bh2[2], bl2[2];
                ldmx2(bBaseHi + nf * (8 * KST * 2) + ks * 32, bh2);
                ldmx2(bBaseLo + nf * (8 * KST * 2) + ks * 32, bl2);
                #pragma unroll
                for (int mf = 0; mf < 4; mf++) {
                    mma_bf16(acc[mf][nf], ahi[mf], bh2);
                    mma_bf16(acc[mf][nf], ahi[mf], bl2);
                    mma_bf16(acc[mf][nf], alo[mf], bh2);
                }
            }
        }
    }

    const float scale = 0.125f;
    float* Sb = g_S + ((size_t)bh << 20);
    const int g  = lane >> 2;
    const int tg = lane & 3;
    #pragma unroll
    for (int mf = 0; mf < 4; mf++) {
        const int mA = r * 128 + mw + mf * 16 + g;
        const int mB = mA + 8;
        #pragma unroll
        for (int nf = 0; nf < 4; nf++) {
            const int nn = c * 128 + nw + nf * 8 + tg * 2;
            *(float2*)&Sb[(size_t)mA * SEQ + nn] =
                make_float2(acc[mf][nf][0] * scale, acc[mf][nf][1] * scale);
            *(float2*)&Sb[(size_t)mB * SEQ + nn] =
                make_float2(acc[mf][nf][2] * scale, acc[mf][nf][3] * scale);
        }
    }
}

// ---------------------------------------------------------------------------
// Softmax: one warp per row. Row i reads S[0..i], writes normalized P hi/lo
// (zero-padded up to the row's tile boundary (r+1)*128 for the PV GEMM).
// ---------------------------------------------------------------------------
__global__ void __launch_bounds__(256) softmax_rows()
{
    const int lane = threadIdx.x & 31;
    const int wrp  = threadIdx.x >> 5;
    const int row  = blockIdx.x * 8 + wrp;        // < NBH*SEQ
    const int bh   = row >> 10;
    const int i    = row & 1023;
    const int r    = i >> 7;
    const int nIt  = (r + 1) * 4;                 // <= 32 iterations of 32 lanes

    const float* Srow = g_S + ((size_t)bh << 20) + (size_t)i * SEQ;
    float sv[32];
    #pragma unroll
    for (int it = 0; it < 32; it++) {
        int j = it * 32 + lane;
        sv[it] = (it < nIt && j <= i) ? Srow[j] : -1e30f;
    }
    float m = -1e30f;
    #pragma unroll
    for (int it = 0; it < 32; it++) m = fmaxf(m, sv[it]);
    #pragma unroll
    for (int off = 16; off; off >>= 1) m = fmaxf(m, __shfl_xor_sync(0xffffffff, m, off));
    float sum = 0.f;
    #pragma unroll
    for (int it = 0; it < 32; it++) {
        float e = __expf(sv[it] - m);             // masked lanes: exp(-huge)=0
        sv[it] = e;
        sum += e;
    }
    #pragma unroll
    for (int off = 16; off; off >>= 1) sum += __shfl_xor_sync(0xffffffff, sum, off);
    const float inv = 1.f / sum;

    __nv_bfloat16* Ph = g_p_hi + ((size_t)bh << 20) + (size_t)i * SEQ;
    __nv_bfloat16* Pl = g_p_lo + ((size_t)bh << 20) + (size_t)i * SEQ;
    #pragma unroll
    for (int it = 0; it < 32; it++) {
        if (it < nIt) {
            int j = it * 32 + lane;
            float p = sv[it] * inv;               // 0 for j > i
            __nv_bfloat16 h = __float2bfloat16(p);
            Ph[j] = h;
            Pl[j] = __float2bfloat16(p - __bfloat162float(h));
        }
    }
}

// ---------------------------------------------------------------------------
// PV GEMM: O[bh][i][d] = sum_j P[i][j] Vt[d][j]   (K loop only over (r+1) tiles)
// grid (8 row-tiles, 64 bh), block 256; warp tile 32(m)x32(n); writes g_att.
// ---------------------------------------------------------------------------
__global__ void __launch_bounds__(256) gemm_pv()
{
    const int r  = blockIdx.x;
    const int bh = blockIdx.y;
    const int b = bh >> 3, h = bh & 7;
    const int tid = threadIdx.x;
    const int w   = tid >> 5;
    const int lane = tid & 31;
    const int mw = (w & 3) * 32;          // m: 128 rows
    const int nw = (w >> 2) * 32;         // n: 64 dims

    __shared__ __align__(16) __nv_bfloat16 sPhi[128 * KST];
    __shared__ __align__(16) __nv_bfloat16 sPlo[128 * KST];
    __shared__ __align__(16) __nv_bfloat16 sVhi[64 * KST];
    __shared__ __align__(16) __nv_bfloat16 sVlo[64 * KST];

    const __nv_bfloat16* Phi = g_p_hi + ((size_t)bh << 20) + (size_t)r * 128 * SEQ;
    const __nv_bfloat16* Plo = g_p_lo + ((size_t)bh << 20) + (size_t)r * 128 * SEQ;
    const __nv_bfloat16* Vhi = g_vt_hi + (size_t)bh * HD * SEQ;
    const __nv_bfloat16* Vlo = g_vt_lo + (size_t)bh * HD * SEQ;

    float acc[2][4][4];
    #pragma unroll
    for (int mf = 0; mf < 2; mf++)
        #pragma unroll
        for (int nf = 0; nf < 4; nf++)
            #pragma unroll
            for (int e = 0; e < 4; e++) acc[mf][nf][e] = 0.f;

    const u32 aBaseHi = smem_u32(sPhi) + (u32)((mw + (lane & 15)) * (KST * 2) + (lane >> 4) * 16);
    const u32 aBaseLo = smem_u32(sPlo) + (u32)((mw + (lane & 15)) * (KST * 2) + (lane >> 4) * 16);
    const u32 bRow    = (u32)((nw + (lane & 7)) * (KST * 2) + ((lane >> 3) & 1) * 16);
    const u32 bBaseHi = smem_u32(sVhi) + bRow;
    const u32 bBaseLo = smem_u32(sVlo) + bRow;

    const int nch = (r + 1) * 4;          // k-chunks of 32
    for (int kc = 0; kc < nch; kc++) {
        const int k0 = kc * 32;
        __syncthreads();
        #pragma unroll
        for (int u = 0; u < 2; u++) {     // P tiles: 2 uint4/thread/array
            int idx = u * 256 + tid;
            int row = idx >> 2, cc = idx & 3;
            size_t src = (size_t)row * SEQ + k0 + cc * 8;
            u32 dst = row * KST + cc * 8;
            *(uint4*)&sPhi[dst] = *(const uint4*)&Phi[src];
            *(uint4*)&sPlo[dst] = *(const uint4*)&Plo[src];
        }
        {                                  // V tiles: 1 uint4/thread/array
            int row = tid >> 2, cc = tid & 3;
            size_t src = (size_t)row * SEQ + k0 + cc * 8;
            u32 dst = row * KST + cc * 8;
            *(uint4*)&sVhi[dst] = *(const uint4*)&Vhi[src];
            *(uint4*)&sVlo[dst] = *(const uint4*)&Vlo[src];
        }
        __syncthreads();

        #pragma unroll
        for (int ks = 0; ks < 2; ks++) {
            u32 ahi[2][4], alo[2][4];
            #pragma unroll
            for (int mf = 0; mf < 2; mf++) {
                ldmx4(aBaseHi + mf * (16 * KST * 2) + ks * 32, ahi[mf]);
                ldmx4(aBaseLo + mf * (16 * KST * 2) + ks * 32, alo[mf]);
            }
            #pragma unroll
            for (int nf = 0; nf < 4; nf++) {
                u32 bh2[2], bl2[2];
                ldmx2(bBaseHi + nf * (8 * KST * 2) + ks * 32, bh2);
                ldmx2(bBaseLo + nf * (8 * KST * 2) + ks * 32, bl2);
                #pragma unroll
                for (int mf = 0; mf < 2; mf++) {
                    mma_bf16(acc[mf][nf], ahi[mf], bh2);
                    mma_bf16(acc[mf][nf], ahi[mf], bl2);
                    mma_bf16(acc[mf][nf], alo[mf], bh2);
                }
            }
        }
    }

    const int g  = lane >> 2;
    const int tg = lane & 3;
    #pragma unroll
    for (int mf = 0; mf < 2; mf++) {
        const int mA = r * 128 + mw + mf * 16 + g;
        const int mB = mA + 8;
        float* oA = g_att + ((size_t)(b * SEQ + mA)) * CH + h * HD;
        float* oB = g_att + ((size_t)(b * SEQ + mB)) * CH + h * HD;
        #pragma unroll
        for (int nf = 0; nf < 4; nf++) {
            const int nn = nw + nf * 8 + tg * 2;
            *(float2*)&oA[nn] = make_float2(acc[mf][nf][0], acc[mf][nf][1]);
            *(float2*)&oB[nn] = make_float2(acc[mf][nf][2], acc[mf][nf][3]);
        }
    }
}

// ---------------------------------------------------------------------------
extern "C" void kernel_launch(void* const* d_in, const int* in_sizes, int n_in,
                              void* d_out, int out_size)
{
    const float* x    = (const float*)d_in[0];
    const float* Wqkv = (const float*)d_in[1];
    const float* bqkv = (const float*)d_in[2];
    const float* Wp   = (const float*)d_in[3];
    const float* bp   = (const float*)d_in[4];
    float* out = (float*)d_out;
    (void)in_sizes; (void)n_in; (void)out_size;

    conv_split<<<(QKV_DIM * CH + 255) / 256, 256>>>(0, Wqkv, QKV_DIM * CH);
    conv_split<<<(CH * CH + 255) / 256, 256>>>(1, Wp, CH * CH);
    convT_x<<<dim3(SEQ / 32, CH / 32, BATCH), dim3(32, 8)>>>(x);

    gemm_mma<0><<<dim3(QKV_DIM / 128, NTOK / 128), 256>>>(bqkv, out);   // -> g_qkv

    relayout_qk<<<(NBH * SEQ * HD) / 256, 256>>>();
    relayout_v<<<dim3(SEQ / 32, HD / 32, NBH), dim3(32, 8)>>>();

    gemm_qk<<<dim3(36, NBH), 256>>>();                                  // -> g_S
    softmax_rows<<<(NBH * SEQ) / 8, 256>>>();                           // -> g_p
    gemm_pv<<<dim3(SEQ / 128, NBH), 256>>>();                           // -> g_att

    conv_split<<<(NTOK * CH + 255) / 256, 256>>>(2, nullptr, NTOK * CH);
    gemm_mma<1><<<dim3(NTOK / 128, CH / 128), 256>>>(bp, out);          // -> out
}

// round 12
// speedup vs baseline: 2.4686x; 1.6755x over previous
#include <cuda_runtime.h>
#include <cuda_bf16.h>

#define BATCH   8
#define CH      512
#define SEQ     1024
#define NH      8
#define HD      64
#define QKV_DIM 1536
#define NTOK    (BATCH * SEQ)     // 8192
#define NBH     (BATCH * NH)      // 64

typedef unsigned long long ull;
typedef unsigned int u32;

__device__ __forceinline__ u32 smem_u32(const void* p) {
    u32 a;
    asm("{ .reg .u64 t; cvta.to.shared.u64 t, %1; cvt.u32.u64 %0, t; }" : "=r"(a) : "l"(p));
    return a;
}

// ---------------- warp MMA helpers (baseline PTX, sm_80+) ----------------
__device__ __forceinline__ void ldmx4(u32 addr, u32* r) {
    asm volatile("ldmatrix.sync.aligned.m8n8.x4.shared.b16 {%0,%1,%2,%3}, [%4];"
                 : "=r"(r[0]), "=r"(r[1]), "=r"(r[2]), "=r"(r[3]) : "r"(addr));
}
__device__ __forceinline__ void ldmx2(u32 addr, u32* r) {
    asm volatile("ldmatrix.sync.aligned.m8n8.x2.shared.b16 {%0,%1}, [%2];"
                 : "=r"(r[0]), "=r"(r[1]) : "r"(addr));
}
__device__ __forceinline__ void mma_bf16(float* d, const u32* a, const u32* b) {
    asm volatile("mma.sync.aligned.m16n8k16.row.col.f32.bf16.bf16.f32 "
                 "{%0,%1,%2,%3}, {%4,%5,%6,%7}, {%8,%9}, {%0,%1,%2,%3};"
                 : "+f"(d[0]), "+f"(d[1]), "+f"(d[2]), "+f"(d[3])
                 : "r"(a[0]), "r"(a[1]), "r"(a[2]), "r"(a[3]), "r"(b[0]), "r"(b[1]));
}
// ---------------- cp.async helpers ----------------
__device__ __forceinline__ void cpa16(u32 dst, const void* src) {
    asm volatile("cp.async.cg.shared.global [%0], [%1], 16;" :: "r"(dst), "l"(src));
}
__device__ __forceinline__ void cp_commit() {
    asm volatile("cp.async.commit_group;" ::: "memory");
}
template <int N>
__device__ __forceinline__ void cp_wait() {
    asm volatile("cp.async.wait_group %0;" :: "n"(N) : "memory");
}

// ---------------- global scratch ----------------
__device__ float g_qkv[NTOK * QKV_DIM];          // [token][3C]
__device__ float g_att[NTOK * CH];               // [token][C]
__device__ __nv_bfloat16 g_xT_hi[NTOK * CH], g_xT_lo[NTOK * CH];
__device__ __nv_bfloat16 g_wq_hi[QKV_DIM * CH], g_wq_lo[QKV_DIM * CH];
__device__ __nv_bfloat16 g_wp_hi[CH * CH],      g_wp_lo[CH * CH];
__device__ __nv_bfloat16 g_at_hi[NTOK * CH],    g_at_lo[NTOK * CH];
__device__ __nv_bfloat16 g_q_hi[NBH * SEQ * HD], g_q_lo[NBH * SEQ * HD];
__device__ __nv_bfloat16 g_k_hi[NBH * SEQ * HD], g_k_lo[NBH * SEQ * HD];
__device__ __nv_bfloat16 g_vt_hi[NBH * HD * SEQ], g_vt_lo[NBH * HD * SEQ];
__device__ float g_S[(size_t)NBH * SEQ * SEQ];
__device__ __nv_bfloat16 g_p_hi[(size_t)NBH * SEQ * SEQ];
__device__ __nv_bfloat16 g_p_lo[(size_t)NBH * SEQ * SEQ];

// ---------------- split-convert: fp32 -> bf16 hi + residual lo ----------------
__global__ void conv_split(int which, const float* __restrict__ src, int n)
{
    int i = blockIdx.x * 256 + threadIdx.x;
    if (i >= n) return;
    __nv_bfloat16 *hi, *lo;
    const float* s = src;
    if (which == 0)      { hi = g_wq_hi; lo = g_wq_lo; }
    else if (which == 1) { hi = g_wp_hi; lo = g_wp_lo; }
    else                 { hi = g_at_hi; lo = g_at_lo; s = g_att; }
    float v = s[i];
    __nv_bfloat16 h = __float2bfloat16(v);
    hi[i] = h;
    lo[i] = __float2bfloat16(v - __bfloat162float(h));
}

__global__ void convT_x(const float* __restrict__ x)
{
    __shared__ float t[32][33];
    const int b  = blockIdx.z;
    const int n0 = blockIdx.x * 32;
    const int c0 = blockIdx.y * 32;
    const int tx = threadIdx.x, ty = threadIdx.y;
    #pragma unroll
    for (int i = 0; i < 4; i++)
        t[ty + i * 8][tx] = x[((size_t)b * CH + c0 + ty + i * 8) * SEQ + n0 + tx];
    __syncthreads();
    #pragma unroll
    for (int i = 0; i < 4; i++) {
        float v = t[tx][ty + i * 8];
        size_t idx = ((size_t)b * SEQ + n0 + ty + i * 8) * CH + c0 + tx;
        __nv_bfloat16 h = __float2bfloat16(v);
        g_xT_hi[idx] = h;
        g_xT_lo[idx] = __float2bfloat16(v - __bfloat162float(h));
    }
}

__global__ void relayout_qk()
{
    int idx = blockIdx.x * 256 + threadIdx.x;
    int d  = idx & 63;
    int n  = (idx >> 6) & 1023;
    int bh = idx >> 16;
    int b = bh >> 3, h = bh & 7;
    size_t src = ((size_t)(b * SEQ + n)) * QKV_DIM + h * HD + d;
    float q = g_qkv[src];
    float k = g_qkv[src + CH];
    __nv_bfloat16 qh = __float2bfloat16(q);
    __nv_bfloat16 kh = __float2bfloat16(k);
    g_q_hi[idx] = qh; g_q_lo[idx] = __float2bfloat16(q - __bfloat162float(qh));
    g_k_hi[idx] = kh; g_k_lo[idx] = __float2bfloat16(k - __bfloat162float(kh));
}

__global__ void relayout_v()
{
    __shared__ float t[32][33];
    const int n0 = blockIdx.x * 32;
    const int d0 = blockIdx.y * 32;
    const int bh = blockIdx.z;
    const int b = bh >> 3, h = bh & 7;
    const int tx = threadIdx.x, ty = threadIdx.y;
    #pragma unroll
    for (int i = 0; i < 4; i++) {
        int n = n0 + ty + i * 8;
        t[ty + i * 8][tx] = g_qkv[((size_t)(b * SEQ + n)) * QKV_DIM + 2 * CH + h * HD + d0 + tx];
    }
    __syncthreads();
    #pragma unroll
    for (int i = 0; i < 4; i++) {
        float v = t[tx][ty + i * 8];
        size_t idx = (size_t)bh * HD * SEQ + (size_t)(d0 + ty + i * 8) * SEQ + n0 + tx;
        __nv_bfloat16 h2 = __float2bfloat16(v);
        g_vt_hi[idx] = h2;
        g_vt_lo[idx] = __float2bfloat16(v - __bfloat162float(h2));
    }
}

#define KST 40            // smem row stride (bf16) for 32-wide K-chunks
#define ARR_B 10240       // bytes per 128xKST bf16 array
#define BUF_B 40960       // 4 arrays per buffer

extern __shared__ unsigned char dynsmem[];

// ---------------------------------------------------------------------------
// Main GEMMs: bf16x3 split mma.sync, cp.async double-buffered.
// ---------------------------------------------------------------------------
template <int MODE>
__global__ void __launch_bounds__(256) gemm_mma(const float* __restrict__ bias,
                                                float* __restrict__ outp)
{
    constexpr int KDIM = 512;
    constexpr int NCHK = KDIM / 32;       // 16
    const int n0  = blockIdx.x * 128;
    const int m0  = blockIdx.y * 128;
    const int tid = threadIdx.x;
    const int w   = tid >> 5;
    const int lane = tid & 31;
    const int mw = (w & 1) * 64;
    const int nw = (w >> 1) * 32;

    const __nv_bfloat16 *Ahi, *Alo, *Bhi, *Blo;
    if (MODE == 0) { Ahi = g_xT_hi; Alo = g_xT_lo; Bhi = g_wq_hi; Blo = g_wq_lo; }
    else           { Ahi = g_wp_hi; Alo = g_wp_lo; Bhi = g_at_hi; Blo = g_at_lo; }

    const u32 sb = smem_u32(dynsmem);

    float acc[4][4][4];
    #pragma unroll
    for (int mf = 0; mf < 4; mf++)
        #pragma unroll
        for (int nf = 0; nf < 4; nf++)
            #pragma unroll
            for (int e = 0; e < 4; e++) acc[mf][nf][e] = 0.f;

    const u32 aOff = (u32)((mw + (lane & 15)) * (KST * 2) + (lane >> 4) * 16);
    const u32 bOff = (u32)((nw + (lane & 7)) * (KST * 2) + ((lane >> 3) & 1) * 16);

    // loader lane mapping: 2 uint4 per thread per array per chunk
    const int lrow0 = tid >> 2, lcc0 = tid & 3;
    const int lrow1 = (256 + tid) >> 2, lcc1 = lcc0;   // rows 64..127

    auto issue = [&](int kc, int buf) {
        const int k0 = kc * 32;
        const u32 base = sb + buf * BUF_B;
        {
            size_t srcA = (size_t)(m0 + lrow0) * KDIM + k0 + lcc0 * 8;
            size_t srcB = (size_t)(n0 + lrow0) * KDIM + k0 + lcc0 * 8;
            u32 d = base + (u32)(2 * (lrow0 * KST + lcc0 * 8));
            cpa16(d,             Ahi + srcA);
            cpa16(d + ARR_B,     Alo + srcA);
            cpa16(d + 2 * ARR_B, Bhi + srcB);
            cpa16(d + 3 * ARR_B, Blo + srcB);
        }
        {
            size_t srcA = (size_t)(m0 + lrow1) * KDIM + k0 + lcc1 * 8;
            size_t srcB = (size_t)(n0 + lrow1) * KDIM + k0 + lcc1 * 8;
            u32 d = base + (u32)(2 * (lrow1 * KST + lcc1 * 8));
            cpa16(d,             Ahi + srcA);
            cpa16(d + ARR_B,     Alo + srcA);
            cpa16(d + 2 * ARR_B, Bhi + srcB);
            cpa16(d + 3 * ARR_B, Blo + srcB);
        }
        cp_commit();
    };

    issue(0, 0);
    for (int kc = 0; kc < NCHK; kc++) {
        const int buf = kc & 1;
        if (kc + 1 < NCHK) { issue(kc + 1, buf ^ 1); cp_wait<1>(); }
        else               { cp_wait<0>(); }
        __syncthreads();

        const u32 base = sb + buf * BUF_B;
        #pragma unroll
        for (int ks = 0; ks < 2; ks++) {
            u32 ahi[4][4], alo[4][4];
            #pragma unroll
            for (int mf = 0; mf < 4; mf++) {
                ldmx4(base + aOff + mf * (16 * KST * 2) + ks * 32, ahi[mf]);
                ldmx4(base + ARR_B + aOff + mf * (16 * KST * 2) + ks * 32, alo[mf]);
            }
            #pragma unroll
            for (int nf = 0; nf < 4; nf++) {
                u32 bh2[2], bl2[2];
                ldmx2(base + 2 * ARR_B + bOff + nf * (8 * KST * 2) + ks * 32, bh2);
                ldmx2(base + 3 * ARR_B + bOff + nf * (8 * KST * 2) + ks * 32, bl2);
                #pragma unroll
                for (int mf = 0; mf < 4; mf++) {
                    mma_bf16(acc[mf][nf], ahi[mf], bh2);
                    mma_bf16(acc[mf][nf], ahi[mf], bl2);
                    mma_bf16(acc[mf][nf], alo[mf], bh2);
                }
            }
        }
        __syncthreads();   // all reads of buf done before it is refilled
    }

    const int g  = lane >> 2;
    const int tg = lane & 3;
    #pragma unroll
    for (int mf = 0; mf < 4; mf++) {
        const int mA = m0 + mw + mf * 16 + g;
        const int mB = mA + 8;
        #pragma unroll
        for (int nf = 0; nf < 4; nf++) {
            const int nn = n0 + nw + nf * 8 + tg * 2;
            if (MODE == 0) {
                float2 bb = *(const float2*)&bias[nn];
                *(float2*)&g_qkv[(size_t)mA * QKV_DIM + nn] =
                    make_float2(acc[mf][nf][0] + bb.x, acc[mf][nf][1] + bb.y);
                *(float2*)&g_qkv[(size_t)mB * QKV_DIM + nn] =
                    make_float2(acc[mf][nf][2] + bb.x, acc[mf][nf][3] + bb.y);
            } else {
                const int bb_ = nn >> 10, np = nn & 1023;
                float biasA = bias[mA], biasB = bias[mB];
                float* ob = outp + (size_t)bb_ * CH * SEQ + np;
                *(float2*)&ob[(size_t)mA * SEQ] =
                    make_float2(acc[mf][nf][0] + biasA, acc[mf][nf][1] + biasA);
                *(float2*)&ob[(size_t)mB * SEQ] =
                    make_float2(acc[mf][nf][2] + biasB, acc[mf][nf][3] + biasB);
            }
        }
    }
}

// ---------------------------------------------------------------------------
// QK^T GEMM: whole K=64 loaded in ONE async group; no k-loop.
// SMEM: 4 arrays of 128 rows x 72 bf16 stride (18432 B each).
// ---------------------------------------------------------------------------
#define QKST  72
#define QARR  18432

__global__ void __launch_bounds__(256) gemm_qk()
{
    const int tId = blockIdx.x;
    const int bh  = blockIdx.y;
    int r = 0, accT = 0;
    while (accT + r + 1 <= tId) { accT += r + 1; r++; }
    const int c = tId - accT;

    const int tid = threadIdx.x;
    const int w   = tid >> 5;
    const int lane = tid & 31;
    const int mw = (w & 1) * 64;
    const int nw = (w >> 1) * 32;

    const __nv_bfloat16* Ahi = g_q_hi + (size_t)bh * SEQ * HD + (size_t)r * 128 * HD;
    const __nv_bfloat16* Alo = g_q_lo + (size_t)bh * SEQ * HD + (size_t)r * 128 * HD;
    const __nv_bfloat16* Bhi = g_k_hi + (size_t)bh * SEQ * HD + (size_t)c * 128 * HD;
    const __nv_bfloat16* Blo = g_k_lo + (size_t)bh * SEQ * HD + (size_t)c * 128 * HD;

    const u32 sb = smem_u32(dynsmem);

    // load entire 128x64 (hi+lo, A+B): 4 uint4 per thread per array
    #pragma unroll
    for (int u = 0; u < 4; u++) {
        int idx = u * 256 + tid;
        int row = idx >> 3, cc = idx & 7;
        size_t src = (size_t)row * HD + cc * 8;
        u32 d = sb + (u32)(row * (QKST * 2) + cc * 16);
        cpa16(d,            Ahi + src);
        cpa16(d + QARR,     Alo + src);
        cpa16(d + 2 * QARR, Bhi + src);
        cpa16(d + 3 * QARR, Blo + src);
    }
    cp_commit();

    float acc[4][4][4];
    #pragma unroll
    for (int mf = 0; mf < 4; mf++)
        #pragma unroll
        for (int nf = 0; nf < 4; nf++)
            #pragma unroll
            for (int e = 0; e < 4; e++) acc[mf][nf][e] = 0.f;

    const u32 aOff = (u32)((mw + (lane & 15)) * (QKST * 2) + (lane >> 4) * 16);
    const u32 bOff = (u32)((nw + (lane & 7)) * (QKST * 2) + ((lane >> 3) & 1) * 16);

    cp_wait<0>();
    __syncthreads();

    #pragma unroll
    for (int ks = 0; ks < 4; ks++) {
        u32 ahi[4][4], alo[4][4];
        #pragma unroll
        for (int mf = 0; mf < 4; mf++) {
            ldmx4(sb + aOff + mf * (16 * QKST * 2) + ks * 32, ahi[mf]);
            ldmx4(sb + QARR + aOff + mf * (16 * QKST * 2) + ks * 32, alo[mf]);
        }
        #pragma unroll
        for (int nf = 0; nf < 4; nf++) {
            u32 bh2[2], bl2[2];
            ldmx2(sb + 2 * QARR + bOff + nf * (8 * QKST * 2) + ks * 32, bh2);
            ldmx2(sb + 3 * QARR + bOff + nf * (8 * QKST * 2) + ks * 32, bl2);
            #pragma unroll
            for (int mf = 0; mf < 4; mf++) {
                mma_bf16(acc[mf][nf], ahi[mf], bh2);
                mma_bf16(acc[mf][nf], ahi[mf], bl2);
                mma_bf16(acc[mf][nf], alo[mf], bh2);
            }
        }
    }

    const float scale = 0.125f;
    float* Sb = g_S + ((size_t)bh << 20);
    const int g  = lane >> 2;
    const int tg = lane & 3;
    #pragma unroll
    for (int mf = 0; mf < 4; mf++) {
        const int mA = r * 128 + mw + mf * 16 + g;
        const int mB = mA + 8;
        #pragma unroll
        for (int nf = 0; nf < 4; nf++) {
            const int nn = c * 128 + nw + nf * 8 + tg * 2;
            *(float2*)&Sb[(size_t)mA * SEQ + nn] =
                make_float2(acc[mf][nf][0] * scale, acc[mf][nf][1] * scale);
            *(float2*)&Sb[(size_t)mB * SEQ + nn] =
                make_float2(acc[mf][nf][2] * scale, acc[mf][nf][3] * scale);
        }
    }
}

// ---------------------------------------------------------------------------
// Softmax: one warp per row (unchanged from R10).
// ---------------------------------------------------------------------------
__global__ void __launch_bounds__(256) softmax_rows()
{
    const int lane = threadIdx.x & 31;
    const int wrp  = threadIdx.x >> 5;
    const int row  = blockIdx.x * 8 + wrp;
    const int bh   = row >> 10;
    const int i    = row & 1023;
    const int r    = i >> 7;
    const int nIt  = (r + 1) * 4;

    const float* Srow = g_S + ((size_t)bh << 20) + (size_t)i * SEQ;
    float sv[32];
    #pragma unroll
    for (int it = 0; it < 32; it++) {
        int j = it * 32 + lane;
        sv[it] = (it < nIt && j <= i) ? Srow[j] : -1e30f;
    }
    float m = -1e30f;
    #pragma unroll
    for (int it = 0; it < 32; it++) m = fmaxf(m, sv[it]);
    #pragma unroll
    for (int off = 16; off; off >>= 1) m = fmaxf(m, __shfl_xor_sync(0xffffffff, m, off));
    float sum = 0.f;
    #pragma unroll
    for (int it = 0; it < 32; it++) {
        float e = __expf(sv[it] - m);
        sv[it] = e;
        sum += e;
    }
    #pragma unroll
    for (int off = 16; off; off >>= 1) sum += __shfl_xor_sync(0xffffffff, sum, off);
    const float inv = 1.f / sum;

    __nv_bfloat16* Ph = g_p_hi + ((size_t)bh << 20) + (size_t)i * SEQ;
    __nv_bfloat16* Pl = g_p_lo + ((size_t)bh << 20) + (size_t)i * SEQ;
    #pragma unroll
    for (int it = 0; it < 32; it++) {
        if (it < nIt) {
            int j = it * 32 + lane;
            float p = sv[it] * inv;
            __nv_bfloat16 h = __float2bfloat16(p);
            Ph[j] = h;
            Pl[j] = __float2bfloat16(p - __bfloat162float(h));
        }
    }
}

// ---------------------------------------------------------------------------
// PV GEMM: cp.async double-buffered over j-chunks of 32.
// Buffer: Phi/Plo 128xKST (10240 B) + Vhi/Vlo 64xKST (5120 B) = 30720 B.
// ---------------------------------------------------------------------------
#define PVBUF 30720

__global__ void __launch_bounds__(256) gemm_pv()
{
    const int r  = blockIdx.x;
    const int bh = blockIdx.y;
    const int b = bh >> 3, h = bh & 7;
    const int tid = threadIdx.x;
    const int w   = tid >> 5;
    const int lane = tid & 31;
    const int mw = (w & 3) * 32;
    const int nw = (w >> 2) * 32;

    const __nv_bfloat16* Phi = g_p_hi + ((size_t)bh << 20) + (size_t)r * 128 * SEQ;
    const __nv_bfloat16* Plo = g_p_lo + ((size_t)bh << 20) + (size_t)r * 128 * SEQ;
    const __nv_bfloat16* Vhi = g_vt_hi + (size_t)bh * HD * SEQ;
    const __nv_bfloat16* Vlo = g_vt_lo + (size_t)bh * HD * SEQ;

    const u32 sb = smem_u32(dynsmem);

    float acc[2][4][4];
    #pragma unroll
    for (int mf = 0; mf < 2; mf++)
        #pragma unroll
        for (int nf = 0; nf < 4; nf++)
            #pragma unroll
            for (int e = 0; e < 4; e++) acc[mf][nf][e] = 0.f;

    const u32 aOff = (u32)((mw + (lane & 15)) * (KST * 2) + (lane >> 4) * 16);
    const u32 bOff = (u32)((nw + (lane & 7)) * (KST * 2) + ((lane >> 3) & 1) * 16);

    const int prow0 = tid >> 2, pcc0 = tid & 3;
    const int prow1 = (256 + tid) >> 2;
    const int vrow  = tid >> 2, vcc = tid & 3;

    auto issue = [&](int kc, int buf) {
        const int k0 = kc * 32;
        const u32 base = sb + buf * PVBUF;
        {
            size_t src = (size_t)prow0 * SEQ + k0 + pcc0 * 8;
            u32 d = base + (u32)(2 * (prow0 * KST + pcc0 * 8));
            cpa16(d,            Phi + src);
            cpa16(d + ARR_B,    Plo + src);
        }
        {
            size_t src = (size_t)prow1 * SEQ + k0 + pcc0 * 8;
            u32 d = base + (u32)(2 * (prow1 * KST + pcc0 * 8));
            cpa16(d,            Phi + src);
            cpa16(d + ARR_B,    Plo + src);
        }
        {
            size_t src = (size_t)vrow * SEQ + k0 + vcc * 8;
            u32 d = base + 2 * ARR_B + (u32)(2 * (vrow * KST + vcc * 8));
            cpa16(d,            Vhi + src);
            cpa16(d + 5120,     Vlo + src);
        }
        cp_commit();
    };

    const int nch = (r + 1) * 4;
    issue(0, 0);
    for (int kc = 0; kc < nch; kc++) {
        const int buf = kc & 1;
        if (kc + 1 < nch) { issue(kc + 1, buf ^ 1); cp_wait<1>(); }
        else              { cp_wait<0>(); }
        __syncthreads();

        const u32 base = sb + buf * PVBUF;
        #pragma unroll
        for (int ks = 0; ks < 2; ks++) {
            u32 ahi[2][4], alo[2][4];
            #pragma unroll
            for (int mf = 0; mf < 2; mf++) {
                ldmx4(base + aOff + mf * (16 * KST * 2) + ks * 32, ahi[mf]);
                ldmx4(base + ARR_B + aOff + mf * (16 * KST * 2) + ks * 32, alo[mf]);
            }
            #pragma unroll
            for (int nf = 0; nf < 4; nf++) {
                u32 bh2[2], bl2[2];
                ldmx2(base + 2 * ARR_B + bOff + nf * (8 * KST * 2) + ks * 32, bh2);
                ldmx2(base + 2 * ARR_B + 5120 + bOff + nf * (8 * KST * 2) + ks * 32, bl2);
                #pragma unroll
                for (int mf = 0; mf < 2; mf++) {
                    mma_bf16(acc[mf][nf], ahi[mf], bh2);
                    mma_bf16(acc[mf][nf], ahi[mf], bl2);
                    mma_bf16(acc[mf][nf], alo[mf], bh2);
                }
            }
        }
        __syncthreads();
    }

    const int g  = lane >> 2;
    const int tg = lane & 3;
    #pragma unroll
    for (int mf = 0; mf < 2; mf++) {
        const int mA = r * 128 + mw + mf * 16 + g;
        const int mB = mA + 8;
        float* oA = g_att + ((size_t)(b * SEQ + mA)) * CH + h * HD;
        float* oB = g_att + ((size_t)(b * SEQ + mB)) * CH + h * HD;
        #pragma unroll
        for (int nf = 0; nf < 4; nf++) {
            const int nn = nw + nf * 8 + tg * 2;
            *(float2*)&oA[nn] = make_float2(acc[mf][nf][0], acc[mf][nf][1]);
            *(float2*)&oB[nn] = make_float2(acc[mf][nf][2], acc[mf][nf][3]);
        }
    }
}

// ---------------------------------------------------------------------------
extern "C" void kernel_launch(void* const* d_in, const int* in_sizes, int n_in,
                              void* d_out, int out_size)
{
    const float* x    = (const float*)d_in[0];
    const float* Wqkv = (const float*)d_in[1];
    const float* bqkv = (const float*)d_in[2];
    const float* Wp   = (const float*)d_in[3];
    const float* bp   = (const float*)d_in[4];
    float* out = (float*)d_out;
    (void)in_sizes; (void)n_in; (void)out_size;

    static int attr_done = 0;
    if (!attr_done) {
        cudaFuncSetAttribute(gemm_mma<0>, cudaFuncAttributeMaxDynamicSharedMemorySize, 2 * BUF_B);
        cudaFuncSetAttribute(gemm_mma<1>, cudaFuncAttributeMaxDynamicSharedMemorySize, 2 * BUF_B);
        cudaFuncSetAttribute(gemm_qk,     cudaFuncAttributeMaxDynamicSharedMemorySize, 4 * QARR);
        cudaFuncSetAttribute(gemm_pv,     cudaFuncAttributeMaxDynamicSharedMemorySize, 2 * PVBUF);
        attr_done = 1;
    }

    conv_split<<<(QKV_DIM * CH + 255) / 256, 256>>>(0, Wqkv, QKV_DIM * CH);
    conv_split<<<(CH * CH + 255) / 256, 256>>>(1, Wp, CH * CH);
    convT_x<<<dim3(SEQ / 32, CH / 32, BATCH), dim3(32, 8)>>>(x);

    gemm_mma<0><<<dim3(QKV_DIM / 128, NTOK / 128), 256, 2 * BUF_B>>>(bqkv, out);

    relayout_qk<<<(NBH * SEQ * HD) / 256, 256>>>();
    relayout_v<<<dim3(SEQ / 32, HD / 32, NBH), dim3(32, 8)>>>();

    gemm_qk<<<dim3(36, NBH), 256, 4 * QARR>>>();
    softmax_rows<<<(NBH * SEQ) / 8, 256>>>();
    gemm_pv<<<dim3(SEQ / 128, NBH), 256, 2 * PVBUF>>>();

    conv_split<<<(NTOK * CH + 255) / 256, 256>>>(2, nullptr, NTOK * CH);
    gemm_mma<1><<<dim3(NTOK / 128, CH / 128), 256, 2 * BUF_B>>>(bp, out);
}

// round 13
// speedup vs baseline: 2.6974x; 1.0927x over previous
#include <cuda_runtime.h>
#include <cuda_bf16.h>

#define BATCH   8
#define CH      512
#define SEQ     1024
#define NH      8
#define HD      64
#define QKV_DIM 1536
#define NTOK    (BATCH * SEQ)     // 8192
#define NBH     (BATCH * NH)      // 64

typedef unsigned long long ull;
typedef unsigned int u32;

__device__ __forceinline__ u32 smem_u32(const void* p) {
    u32 a;
    asm("{ .reg .u64 t; cvta.to.shared.u64 t, %1; cvt.u32.u64 %0, t; }" : "=r"(a) : "l"(p));
    return a;
}

// ---------------- warp MMA helpers (baseline PTX, sm_80+) ----------------
__device__ __forceinline__ void ldmx4(u32 addr, u32* r) {
    asm volatile("ldmatrix.sync.aligned.m8n8.x4.shared.b16 {%0,%1,%2,%3}, [%4];"
                 : "=r"(r[0]), "=r"(r[1]), "=r"(r[2]), "=r"(r[3]) : "r"(addr));
}
__device__ __forceinline__ void ldmx2(u32 addr, u32* r) {
    asm volatile("ldmatrix.sync.aligned.m8n8.x2.shared.b16 {%0,%1}, [%2];"
                 : "=r"(r[0]), "=r"(r[1]) : "r"(addr));
}
__device__ __forceinline__ void mma_bf16(float* d, const u32* a, const u32* b) {
    asm volatile("mma.sync.aligned.m16n8k16.row.col.f32.bf16.bf16.f32 "
                 "{%0,%1,%2,%3}, {%4,%5,%6,%7}, {%8,%9}, {%0,%1,%2,%3};"
                 : "+f"(d[0]), "+f"(d[1]), "+f"(d[2]), "+f"(d[3])
                 : "r"(a[0]), "r"(a[1]), "r"(a[2]), "r"(a[3]), "r"(b[0]), "r"(b[1]));
}
// ---------------- cp.async helpers ----------------
__device__ __forceinline__ void cpa16(u32 dst, const void* src) {
    asm volatile("cp.async.cg.shared.global [%0], [%1], 16;" :: "r"(dst), "l"(src));
}
__device__ __forceinline__ void cp_commit() {
    asm volatile("cp.async.commit_group;" ::: "memory");
}
template <int N>
__device__ __forceinline__ void cp_wait() {
    asm volatile("cp.async.wait_group %0;" :: "n"(N) : "memory");
}

// ---------------- global scratch ----------------
__device__ __nv_bfloat16 g_xT_hi[NTOK * CH], g_xT_lo[NTOK * CH];
__device__ __nv_bfloat16 g_wq_hi[QKV_DIM * CH], g_wq_lo[QKV_DIM * CH];
__device__ __nv_bfloat16 g_wp_hi[CH * CH],      g_wp_lo[CH * CH];
__device__ __nv_bfloat16 g_at_hi[NTOK * CH],    g_at_lo[NTOK * CH];
__device__ __nv_bfloat16 g_q_hi[NBH * SEQ * HD], g_q_lo[NBH * SEQ * HD];   // [bh][n][d]
__device__ __nv_bfloat16 g_k_hi[NBH * SEQ * HD], g_k_lo[NBH * SEQ * HD];   // [bh][n][d]
__device__ __nv_bfloat16 g_vt_hi[NBH * HD * SEQ], g_vt_lo[NBH * HD * SEQ]; // [bh][d][n]
__device__ float g_S[(size_t)NBH * SEQ * SEQ];
__device__ __nv_bfloat16 g_p_hi[(size_t)NBH * SEQ * SEQ];
__device__ __nv_bfloat16 g_p_lo[(size_t)NBH * SEQ * SEQ];

// ---------------- split store helpers ----------------
__device__ __forceinline__ void store_split2(__nv_bfloat16* hi, __nv_bfloat16* lo,
                                             size_t idx, float va, float vb)
{
    __nv_bfloat16 ha = __float2bfloat16(va), hb = __float2bfloat16(vb);
    __nv_bfloat162 hv; hv.x = ha; hv.y = hb;
    __nv_bfloat162 lv;
    lv.x = __float2bfloat16(va - __bfloat162float(ha));
    lv.y = __float2bfloat16(vb - __bfloat162float(hb));
    *(__nv_bfloat162*)(hi + idx) = hv;
    *(__nv_bfloat162*)(lo + idx) = lv;
}
__device__ __forceinline__ void store_split1(__nv_bfloat16* hi, __nv_bfloat16* lo,
                                             size_t idx, float v)
{
    __nv_bfloat16 h = __float2bfloat16(v);
    hi[idx] = h;
    lo[idx] = __float2bfloat16(v - __bfloat162float(h));
}

// qkv epilogue dispatch: token t, feature pair (j, j+1) -> q/k/vt splits
__device__ __forceinline__ void qkv_store(int t, int j, float va, float vb)
{
    const int b = t >> 10, n = t & 1023;
    if (j < 1024) {
        const int jj = j & 511;
        const int bh = b * 8 + (jj >> 6);
        const int d  = jj & 63;
        const size_t idx = ((size_t)bh << 16) + ((size_t)n << 6) + d;
        if (j < 512) store_split2(g_q_hi, g_q_lo, idx, va, vb);
        else         store_split2(g_k_hi, g_k_lo, idx, va, vb);
    } else {
        const int jj = j - 1024;
        const int bh = b * 8 + (jj >> 6);
        const int d  = jj & 63;
        const size_t idx = ((size_t)bh << 16) + ((size_t)d << 10) + n;
        store_split1(g_vt_hi, g_vt_lo, idx, va);
        store_split1(g_vt_hi, g_vt_lo, idx + 1024, vb);
    }
}

// ---------------- weight split-convert ----------------
__global__ void conv_split(int which, const float* __restrict__ src, int n)
{
    int i = blockIdx.x * 256 + threadIdx.x;
    if (i >= n) return;
    __nv_bfloat16 *hi = which ? g_wp_hi : g_wq_hi;
    __nv_bfloat16 *lo = which ? g_wp_lo : g_wq_lo;
    float v = src[i];
    __nv_bfloat16 h = __float2bfloat16(v);
    hi[i] = h;
    lo[i] = __float2bfloat16(v - __bfloat162float(h));
}

// ---------------- transpose-convert x[b][c][n] -> xT[(b,n)][c] hi/lo ----------------
__global__ void convT_x(const float* __restrict__ x)
{
    __shared__ float t[32][33];
    const int b  = blockIdx.z;
    const int n0 = blockIdx.x * 32;
    const int c0 = blockIdx.y * 32;
    const int tx = threadIdx.x, ty = threadIdx.y;
    #pragma unroll
    for (int i = 0; i < 4; i++)
        t[ty + i * 8][tx] = x[((size_t)b * CH + c0 + ty + i * 8) * SEQ + n0 + tx];
    __syncthreads();
    #pragma unroll
    for (int i = 0; i < 4; i++) {
        float v = t[tx][ty + i * 8];
        size_t idx = ((size_t)b * SEQ + n0 + ty + i * 8) * CH + c0 + tx;
        __nv_bfloat16 h = __float2bfloat16(v);
        g_xT_hi[idx] = h;
        g_xT_lo[idx] = __float2bfloat16(v - __bfloat162float(h));
    }
}

#define KST 40            // smem row stride (bf16) for 32-wide K-chunks
#define ARR_B 10240       // bytes per 128xKST bf16 array
#define BUF_B 40960       // 4 arrays per buffer
#define NSTAGE 4

extern __shared__ unsigned char dynsmem[];

// ---------------------------------------------------------------------------
// Main GEMMs: bf16x3 split mma.sync, 4-stage cp.async ring, 1 sync/iter.
// MODE 0: A=xT (m=tok), B=Wqkv (n=j)  -> epilogue writes q/k/vt splits directly
// MODE 1: A=Wp (m=ch),  B=att (n=tok) -> epilogue writes final output (NCHW)
// ---------------------------------------------------------------------------
template <int MODE>
__global__ void __launch_bounds__(256) gemm_mma(const float* __restrict__ bias,
                                                float* __restrict__ outp)
{
    constexpr int KDIM = 512;
    constexpr int NCHK = KDIM / 32;       // 16
    const int n0  = blockIdx.x * 128;
    const int m0  = blockIdx.y * 128;
    const int tid = threadIdx.x;
    const int w   = tid >> 5;
    const int lane = tid & 31;
    const int mw = (w & 1) * 64;
    const int nw = (w >> 1) * 32;

    const __nv_bfloat16 *Ahi, *Alo, *Bhi, *Blo;
    if (MODE == 0) { Ahi = g_xT_hi; Alo = g_xT_lo; Bhi = g_wq_hi; Blo = g_wq_lo; }
    else           { Ahi = g_wp_hi; Alo = g_wp_lo; Bhi = g_at_hi; Blo = g_at_lo; }

    const u32 sb = smem_u32(dynsmem);

    float acc[4][4][4];
    #pragma unroll
    for (int mf = 0; mf < 4; mf++)
        #pragma unroll
        for (int nf = 0; nf < 4; nf++)
            #pragma unroll
            for (int e = 0; e < 4; e++) acc[mf][nf][e] = 0.f;

    const u32 aOff = (u32)((mw + (lane & 15)) * (KST * 2) + (lane >> 4) * 16);
    const u32 bOff = (u32)((nw + (lane & 7)) * (KST * 2) + ((lane >> 3) & 1) * 16);

    const int lrow0 = tid >> 2, lcc0 = tid & 3;
    const int lrow1 = lrow0 + 64;

    auto issue = [&](int kc) {
        const int k0 = kc * 32;
        const u32 base = sb + (kc & 3) * BUF_B;
        {
            size_t srcA = (size_t)(m0 + lrow0) * KDIM + k0 + lcc0 * 8;
            size_t srcB = (size_t)(n0 + lrow0) * KDIM + k0 + lcc0 * 8;
            u32 d = base + (u32)(2 * (lrow0 * KST + lcc0 * 8));
            cpa16(d,             Ahi + srcA);
            cpa16(d + ARR_B,     Alo + srcA);
            cpa16(d + 2 * ARR_B, Bhi + srcB);
            cpa16(d + 3 * ARR_B, Blo + srcB);
        }
        {
            size_t srcA = (size_t)(m0 + lrow1) * KDIM + k0 + lcc0 * 8;
            size_t srcB = (size_t)(n0 + lrow1) * KDIM + k0 + lcc0 * 8;
            u32 d = base + (u32)(2 * (lrow1 * KST + lcc0 * 8));
            cpa16(d,             Ahi + srcA);
            cpa16(d + ARR_B,     Alo + srcA);
            cpa16(d + 2 * ARR_B, Bhi + srcB);
            cpa16(d + 3 * ARR_B, Blo + srcB);
        }
        cp_commit();
    };

    issue(0); issue(1); issue(2);
    for (int kc = 0; kc < NCHK; kc++) {
        cp_wait<2>();          // group kc complete (oldest beyond the 2 newest)
        __syncthreads();       // also orders buffer reuse: next issue targets kc-1's buf

        const u32 base = sb + (kc & 3) * BUF_B;
        #pragma unroll
        for (int ks = 0; ks < 2; ks++) {
            u32 ahi[4][4], alo[4][4];
            #pragma unroll
            for (int mf = 0; mf < 4; mf++) {
                ldmx4(base + aOff + mf * (16 * KST * 2) + ks * 32, ahi[mf]);
                ldmx4(base + ARR_B + aOff + mf * (16 * KST * 2) + ks * 32, alo[mf]);
            }
            #pragma unroll
            for (int nf = 0; nf < 4; nf++) {
                u32 bh2[2], bl2[2];
                ldmx2(base + 2 * ARR_B + bOff + nf * (8 * KST * 2) + ks * 32, bh2);
                ldmx2(base + 3 * ARR_B + bOff + nf * (8 * KST * 2) + ks * 32, bl2);
                #pragma unroll
                for (int mf = 0; mf < 4; mf++) {
                    mma_bf16(acc[mf][nf], ahi[mf], bh2);
                    mma_bf16(acc[mf][nf], ahi[mf], bl2);
                    mma_bf16(acc[mf][nf], alo[mf], bh2);
                }
            }
        }
        if (kc + 3 < NCHK) issue(kc + 3);
        else               cp_commit();    // keep group accounting aligned
    }

    const int g  = lane >> 2;
    const int tg = lane & 3;
    #pragma unroll
    for (int mf = 0; mf < 4; mf++) {
        const int mA = m0 + mw + mf * 16 + g;
        const int mB = mA + 8;
        #pragma unroll
        for (int nf = 0; nf < 4; nf++) {
            const int nn = n0 + nw + nf * 8 + tg * 2;
            if (MODE == 0) {
                float2 bb = *(const float2*)&bias[nn];
                qkv_store(mA, nn, acc[mf][nf][0] + bb.x, acc[mf][nf][1] + bb.y);
                qkv_store(mB, nn, acc[mf][nf][2] + bb.x, acc[mf][nf][3] + bb.y);
            } else {
                const int bb_ = nn >> 10, np = nn & 1023;
                float biasA = bias[mA], biasB = bias[mB];
                float* ob = outp + (size_t)bb_ * CH * SEQ + np;
                *(float2*)&ob[(size_t)mA * SEQ] =
                    make_float2(acc[mf][nf][0] + biasA, acc[mf][nf][1] + biasA);
                *(float2*)&ob[(size_t)mB * SEQ] =
                    make_float2(acc[mf][nf][2] + biasB, acc[mf][nf][3] + biasB);
            }
        }
    }
}

// ---------------------------------------------------------------------------
// QK^T GEMM: whole K=64 loaded in ONE async group; no k-loop.
// ---------------------------------------------------------------------------
#define QKST  72
#define QARR  18432

__global__ void __launch_bounds__(256) gemm_qk()
{
    const int tId = blockIdx.x;
    const int bh  = blockIdx.y;
    int r = 0, accT = 0;
    while (accT + r + 1 <= tId) { accT += r + 1; r++; }
    const int c = tId - accT;

    const int tid = threadIdx.x;
    const int w   = tid >> 5;
    const int lane = tid & 31;
    const int mw = (w & 1) * 64;
    const int nw = (w >> 1) * 32;

    const __nv_bfloat16* Ahi = g_q_hi + (size_t)bh * SEQ * HD + (size_t)r * 128 * HD;
    const __nv_bfloat16* Alo = g_q_lo + (size_t)bh * SEQ * HD + (size_t)r * 128 * HD;
    const __nv_bfloat16* Bhi = g_k_hi + (size_t)bh * SEQ * HD + (size_t)c * 128 * HD;
    const __nv_bfloat16* Blo = g_k_lo + (size_t)bh * SEQ * HD + (size_t)c * 128 * HD;

    const u32 sb = smem_u32(dynsmem);

    #pragma unroll
    for (int u = 0; u < 4; u++) {
        int idx = u * 256 + tid;
        int row = idx >> 3, cc = idx & 7;
        size_t src = (size_t)row * HD + cc * 8;
        u32 d = sb + (u32)(row * (QKST * 2) + cc * 16);
        cpa16(d,            Ahi + src);
        cpa16(d + QARR,     Alo + src);
        cpa16(d + 2 * QARR, Bhi + src);
        cpa16(d + 3 * QARR, Blo + src);
    }
    cp_commit();

    float acc[4][4][4];
    #pragma unroll
    for (int mf = 0; mf < 4; mf++)
        #pragma unroll
        for (int nf = 0; nf < 4; nf++)
            #pragma unroll
            for (int e = 0; e < 4; e++) acc[mf][nf][e] = 0.f;

    const u32 aOff = (u32)((mw + (lane & 15)) * (QKST * 2) + (lane >> 4) * 16);
    const u32 bOff = (u32)((nw + (lane & 7)) * (QKST * 2) + ((lane >> 3) & 1) * 16);

    cp_wait<0>();
    __syncthreads();

    #pragma unroll
    for (int ks = 0; ks < 4; ks++) {
        u32 ahi[4][4], alo[4][4];
        #pragma unroll
        for (int mf = 0; mf < 4; mf++) {
            ldmx4(sb + aOff + mf * (16 * QKST * 2) + ks * 32, ahi[mf]);
            ldmx4(sb + QARR + aOff + mf * (16 * QKST * 2) + ks * 32, alo[mf]);
        }
        #pragma unroll
        for (int nf = 0; nf < 4; nf++) {
            u32 bh2[2], bl2[2];
            ldmx2(sb + 2 * QARR + bOff + nf * (8 * QKST * 2) + ks * 32, bh2);
            ldmx2(sb + 3 * QARR + bOff + nf * (8 * QKST * 2) + ks * 32, bl2);
            #pragma unroll
            for (int mf = 0; mf < 4; mf++) {
                mma_bf16(acc[mf][nf], ahi[mf], bh2);
                mma_bf16(acc[mf][nf], ahi[mf], bl2);
                mma_bf16(acc[mf][nf], alo[mf], bh2);
            }
        }
    }

    const float scale = 0.125f;
    float* Sb = g_S + ((size_t)bh << 20);
    const int g  = lane >> 2;
    const int tg = lane & 3;
    #pragma unroll
    for (int mf = 0; mf < 4; mf++) {
        const int mA = r * 128 + mw + mf * 16 + g;
        const int mB = mA + 8;
        #pragma unroll
        for (int nf = 0; nf < 4; nf++) {
            const int nn = c * 128 + nw + nf * 8 + tg * 2;
            *(float2*)&Sb[(size_t)mA * SEQ + nn] =
                make_float2(acc[mf][nf][0] * scale, acc[mf][nf][1] * scale);
            *(float2*)&Sb[(size_t)mB * SEQ + nn] =
                make_float2(acc[mf][nf][2] * scale, acc[mf][nf][3] * scale);
        }
    }
}

// ---------------------------------------------------------------------------
// Softmax: one warp per row.
// ---------------------------------------------------------------------------
__global__ void __launch_bounds__(256) softmax_rows()
{
    const int lane = threadIdx.x & 31;
    const int wrp  = threadIdx.x >> 5;
    const int row  = blockIdx.x * 8 + wrp;
    const int bh   = row >> 10;
    const int i    = row & 1023;
    const int r    = i >> 7;
    const int nIt  = (r + 1) * 4;

    const float* Srow = g_S + ((size_t)bh << 20) + (size_t)i * SEQ;
    float sv[32];
    #pragma unroll
    for (int it = 0; it < 32; it++) {
        int j = it * 32 + lane;
        sv[it] = (it < nIt && j <= i) ? Srow[j] : -1e30f;
    }
    float m = -1e30f;
    #pragma unroll
    for (int it = 0; it < 32; it++) m = fmaxf(m, sv[it]);
    #pragma unroll
    for (int off = 16; off; off >>= 1) m = fmaxf(m, __shfl_xor_sync(0xffffffff, m, off));
    float sum = 0.f;
    #pragma unroll
    for (int it = 0; it < 32; it++) {
        float e = __expf(sv[it] - m);
        sv[it] = e;
        sum += e;
    }
    #pragma unroll
    for (int off = 16; off; off >>= 1) sum += __shfl_xor_sync(0xffffffff, sum, off);
    const float inv = 1.f / sum;

    __nv_bfloat16* Ph = g_p_hi + ((size_t)bh << 20) + (size_t)i * SEQ;
    __nv_bfloat16* Pl = g_p_lo + ((size_t)bh << 20) + (size_t)i * SEQ;
    #pragma unroll
    for (int it = 0; it < 32; it++) {
        if (it < nIt) {
            int j = it * 32 + lane;
            float p = sv[it] * inv;
            __nv_bfloat16 h = __float2bfloat16(p);
            Ph[j] = h;
            Pl[j] = __float2bfloat16(p - __bfloat162float(h));
        }
    }
}

// ---------------------------------------------------------------------------
// PV GEMM: 4-stage cp.async ring; epilogue writes g_at hi/lo splits directly.
// Buffer: Phi/Plo 128xKST + Vhi/Vlo 64xKST = 30720 B.
// ---------------------------------------------------------------------------
#define PVBUF 30720

__global__ void __launch_bounds__(256) gemm_pv()
{
    const int r  = blockIdx.x;
    const int bh = blockIdx.y;
    const int b = bh >> 3, h = bh & 7;
    const int tid = threadIdx.x;
    const int w   = tid >> 5;
    const int lane = tid & 31;
    const int mw = (w & 3) * 32;
    const int nw = (w >> 2) * 32;

    const __nv_bfloat16* Phi = g_p_hi + ((size_t)bh << 20) + (size_t)r * 128 * SEQ;
    const __nv_bfloat16* Plo = g_p_lo + ((size_t)bh << 20) + (size_t)r * 128 * SEQ;
    const __nv_bfloat16* Vhi = g_vt_hi + (size_t)bh * HD * SEQ;
    const __nv_bfloat16* Vlo = g_vt_lo + (size_t)bh * HD * SEQ;

    const u32 sb = smem_u32(dynsmem);

    float acc[2][4][4];
    #pragma unroll
    for (int mf = 0; mf < 2; mf++)
        #pragma unroll
        for (int nf = 0; nf < 4; nf++)
            #pragma unroll
            for (int e = 0; e < 4; e++) acc[mf][nf][e] = 0.f;

    const u32 aOff = (u32)((mw + (lane & 15)) * (KST * 2) + (lane >> 4) * 16);
    const u32 bOff = (u32)((nw + (lane & 7)) * (KST * 2) + ((lane >> 3) & 1) * 16);

    const int prow0 = tid >> 2, pcc0 = tid & 3;
    const int prow1 = prow0 + 64;
    const int vrow  = tid >> 2, vcc = tid & 3;

    auto issue = [&](int kc) {
        const int k0 = kc * 32;
        const u32 base = sb + (kc & 3) * PVBUF;
        {
            size_t src = (size_t)prow0 * SEQ + k0 + pcc0 * 8;
            u32 d = base + (u32)(2 * (prow0 * KST + pcc0 * 8));
            cpa16(d,         Phi + src);
            cpa16(d + ARR_B, Plo + src);
        }
        {
            size_t src = (size_t)prow1 * SEQ + k0 + pcc0 * 8;
            u32 d = base + (u32)(2 * (prow1 * KST + pcc0 * 8));
            cpa16(d,         Phi + src);
            cpa16(d + ARR_B, Plo + src);
        }
        {
            size_t src = (size_t)vrow * SEQ + k0 + vcc * 8;
            u32 d = base + 2 * ARR_B + (u32)(2 * (vrow * KST + vcc * 8));
            cpa16(d,        Vhi + src);
            cpa16(d + 5120, Vlo + src);
        }
        cp_commit();
    };

    const int nch = (r + 1) * 4;   // >= 4 always
    issue(0); issue(1); issue(2);
    for (int kc = 0; kc < nch; kc++) {
        cp_wait<2>();
        __syncthreads();

        const u32 base = sb + (kc & 3) * PVBUF;
        #pragma unroll
        for (int ks = 0; ks < 2; ks++) {
            u32 ahi[2][4], alo[2][4];
            #pragma unroll
            for (int mf = 0; mf < 2; mf++) {
                ldmx4(base + aOff + mf * (16 * KST * 2) + ks * 32, ahi[mf]);
                ldmx4(base + ARR_B + aOff + mf * (16 * KST * 2) + ks * 32, alo[mf]);
            }
            #pragma unroll
            for (int nf = 0; nf < 4; nf++) {
                u32 bh2[2], bl2[2];
                ldmx2(base + 2 * ARR_B + bOff + nf * (8 * KST * 2) + ks * 32, bh2);
                ldmx2(base + 2 * ARR_B + 5120 + bOff + nf * (8 * KST * 2) + ks * 32, bl2);
                #pragma unroll
                for (int mf = 0; mf < 2; mf++) {
                    mma_bf16(acc[mf][nf], ahi[mf], bh2);
                    mma_bf16(acc[mf][nf], ahi[mf], bl2);
                    mma_bf16(acc[mf][nf], alo[mf], bh2);
                }
            }
        }
        if (kc + 3 < nch) issue(kc + 3);
        else              cp_commit();
    }

    const int g  = lane >> 2;
    const int tg = lane & 3;
    #pragma unroll
    for (int mf = 0; mf < 2; mf++) {
        const int mA = r * 128 + mw + mf * 16 + g;
        const int mB = mA + 8;
        const size_t oA = ((size_t)(b * SEQ + mA)) * CH + h * HD;
        const size_t oB = ((size_t)(b * SEQ + mB)) * CH + h * HD;
        #pragma unroll
        for (int nf = 0; nf < 4; nf++) {
            const int nn = nw + nf * 8 + tg * 2;
            store_split2(g_at_hi, g_at_lo, oA + nn, acc[mf][nf][0], acc[mf][nf][1]);
            store_split2(g_at_hi, g_at_lo, oB + nn, acc[mf][nf][2], acc[mf][nf][3]);
        }
    }
}

// ---------------------------------------------------------------------------
extern "C" void kernel_launch(void* const* d_in, const int* in_sizes, int n_in,
                              void* d_out, int out_size)
{
    const float* x    = (const float*)d_in[0];
    const float* Wqkv = (const float*)d_in[1];
    const float* bqkv = (const float*)d_in[2];
    const float* Wp   = (const float*)d_in[3];
    const float* bp   = (const float*)d_in[4];
    float* out = (float*)d_out;
    (void)in_sizes; (void)n_in; (void)out_size;

    static int attr_done = 0;
    if (!attr_done) {
        cudaFuncSetAttribute(gemm_mma<0>, cudaFuncAttributeMaxDynamicSharedMemorySize, NSTAGE * BUF_B);
        cudaFuncSetAttribute(gemm_mma<1>, cudaFuncAttributeMaxDynamicSharedMemorySize, NSTAGE * BUF_B);
        cudaFuncSetAttribute(gemm_qk,     cudaFuncAttributeMaxDynamicSharedMemorySize, 4 * QARR);
        cudaFuncSetAttribute(gemm_pv,     cudaFuncAttributeMaxDynamicSharedMemorySize, NSTAGE * PVBUF);
        attr_done = 1;
    }

    conv_split<<<(QKV_DIM * CH + 255) / 256, 256>>>(0, Wqkv, QKV_DIM * CH);
    conv_split<<<(CH * CH + 255) / 256, 256>>>(1, Wp, CH * CH);
    convT_x<<<dim3(SEQ / 32, CH / 32, BATCH), dim3(32, 8)>>>(x);

    gemm_mma<0><<<dim3(QKV_DIM / 128, NTOK / 128), 256, NSTAGE * BUF_B>>>(bqkv, out);  // -> q/k/vt splits

    gemm_qk<<<dim3(36, NBH), 256, 4 * QARR>>>();                                       // -> g_S
    softmax_rows<<<(NBH * SEQ) / 8, 256>>>();                                          // -> g_p
    gemm_pv<<<dim3(SEQ / 128, NBH), 256, NSTAGE * PVBUF>>>();                          // -> g_at splits

    gemm_mma<1><<<dim3(NTOK / 128, CH / 128), 256, NSTAGE * BUF_B>>>(bp, out);         // -> out
}